// round 1
// baseline (speedup 1.0000x reference)
#include <cuda_runtime.h>
#include <math.h>

// ---------------- problem constants ----------------
#define N0   4096
#define INC  128
#define HC   512
#define OC   64
#define KP1  2000
#define KP2  1000
#define KP3  500

#define ACT_NONE 0
#define ACT_RELU 1
#define ACT_SIGM 2

// ---------------- scratch (device globals; allocation-free) ----------------
__device__ float g_A0 [(size_t)N0*N0];      // 64 MB  level-0 adjacency
__device__ float g_ApI[(size_t)N0*N0];      // 64 MB  A + I temp
__device__ float g_Aug[(size_t)N0*N0];      // 64 MB  augmented adjacency
__device__ float g_A1 [(size_t)KP1*KP1];
__device__ float g_A2 [(size_t)KP2*KP2];
__device__ float g_A3 [(size_t)KP3*KP3];
__device__ float g_h0 [(size_t)N0*HC];
__device__ float g_h1 [(size_t)KP1*HC];
__device__ float g_h2 [(size_t)KP2*HC];
__device__ float g_h3 [(size_t)KP3*HC];
__device__ float g_hb [(size_t)KP1*HC];     // up-path ping buffer (max 2000x512)
__device__ float g_xw [(size_t)N0*HC];
__device__ float g_z  [(size_t)N0*HC];
__device__ float g_t  [(size_t)N0*HC];
__device__ float g_u  [(size_t)N0*HC];
__device__ float g_dis[N0];
__device__ float g_sc [N0];
__device__ float g_pn [1];
__device__ int   g_perm0[KP1];
__device__ int   g_perm1[KP2];
__device__ int   g_perm2[KP3];

// ---------------- SGEMM: C(MxN) = A(MxK) @ B(KxN), row-major fp32 ----------------
// 128x128 block, 8x8 per thread, BK=8, 256 threads. Requires K%4==0 and N%4==0
// (true for every GEMM in this pipeline); handles arbitrary M/N/K edges.
__global__ void __launch_bounds__(256) sgemm(int M, int N, int K,
                                             const float* __restrict__ A,
                                             const float* __restrict__ B,
                                             float* __restrict__ C) {
    __shared__ float As[8][128];
    __shared__ float Bs[8][128];
    const int tid  = threadIdx.x;
    const int tx   = tid & 15;         // 0..15 -> N dir
    const int ty   = tid >> 4;         // 0..15 -> M dir
    const int row0 = blockIdx.y * 128;
    const int col0 = blockIdx.x * 128;
    const int a_row = tid >> 1, a_col = (tid & 1) << 2;     // A tile: 128 rows x 8 k
    const int b_row = tid >> 5, b_col = (tid & 31) << 2;    // B tile: 8 k x 128 cols

    float acc[8][8];
#pragma unroll
    for (int i = 0; i < 8; i++)
#pragma unroll
        for (int j = 0; j < 8; j++) acc[i][j] = 0.f;

    for (int kk = 0; kk < K; kk += 8) {
        float4 av = make_float4(0.f, 0.f, 0.f, 0.f);
        {
            int gm = row0 + a_row, gk = kk + a_col;
            if (gm < M && gk < K)   // K%4==0, gk%4==0 => full float4 in-bounds
                av = *reinterpret_cast<const float4*>(A + (size_t)gm * K + gk);
        }
        As[a_col + 0][a_row] = av.x;
        As[a_col + 1][a_row] = av.y;
        As[a_col + 2][a_row] = av.z;
        As[a_col + 3][a_row] = av.w;

        float4 bv = make_float4(0.f, 0.f, 0.f, 0.f);
        {
            int gk = kk + b_row, gn = col0 + b_col;
            if (gk < K && gn < N)   // N%4==0, gn%4==0 => full float4 in-bounds
                bv = *reinterpret_cast<const float4*>(B + (size_t)gk * N + gn);
        }
        *reinterpret_cast<float4*>(&Bs[b_row][b_col]) = bv;
        __syncthreads();

#pragma unroll
        for (int k = 0; k < 8; k++) {
            float4 a0 = *reinterpret_cast<const float4*>(&As[k][ty * 8]);
            float4 a1 = *reinterpret_cast<const float4*>(&As[k][ty * 8 + 4]);
            float4 b0 = *reinterpret_cast<const float4*>(&Bs[k][tx * 8]);
            float4 b1 = *reinterpret_cast<const float4*>(&Bs[k][tx * 8 + 4]);
            float a[8] = {a0.x, a0.y, a0.z, a0.w, a1.x, a1.y, a1.z, a1.w};
            float b[8] = {b0.x, b0.y, b0.z, b0.w, b1.x, b1.y, b1.z, b1.w};
#pragma unroll
            for (int i = 0; i < 8; i++)
#pragma unroll
                for (int j = 0; j < 8; j++) acc[i][j] += a[i] * b[j];
        }
        __syncthreads();
    }

#pragma unroll
    for (int i = 0; i < 8; i++) {
        int gm = row0 + ty * 8 + i;
        if (gm >= M) continue;
        float* Cr = C + (size_t)gm * N;
#pragma unroll
        for (int j = 0; j < 8; j++) {
            int gn = col0 + tx * 8 + j;
            if (gn < N) Cr[gn] = acc[i][j];
        }
    }
}

// ---------------- elementwise / graph kernels ----------------
__global__ void k_edges(const int* __restrict__ ei, int E, float* __restrict__ A) {
    int e = blockIdx.x * blockDim.x + threadIdx.x;
    if (e >= E) return;
    int s = ei[e], d = ei[E + e];
    A[(size_t)s * N0 + d] = 1.f;
    A[(size_t)d * N0 + s] = 1.f;
}

// dis[i] = rsqrt(rowsum(A)[i] + 1)
__global__ void k_dis(const float* __restrict__ A, int n, float* __restrict__ dis) {
    __shared__ float red[256];
    int row = blockIdx.x;
    const float* Ar = A + (size_t)row * n;
    float s = 0.f;
    for (int j = threadIdx.x; j < n; j += 256) s += Ar[j];
    red[threadIdx.x] = s;
    __syncthreads();
    for (int o = 128; o > 0; o >>= 1) {
        if (threadIdx.x < o) red[threadIdx.x] += red[threadIdx.x + o];
        __syncthreads();
    }
    if (threadIdx.x == 0) dis[row] = rsqrtf(red[0] + 1.0f);
}

__global__ void k_scale(const float* __restrict__ xw, const float* __restrict__ dis,
                        int n, int C, float* __restrict__ z) {
    int i = blockIdx.x * blockDim.x + threadIdx.x;
    if (i >= n * C) return;
    z[i] = dis[i / C] * xw[i];
}

__global__ void k_epilogue(const float* __restrict__ t, const float* __restrict__ z,
                           const float* __restrict__ dis, const float* __restrict__ b,
                           int n, int C, float* __restrict__ out, int act) {
    int i = blockIdx.x * blockDim.x + threadIdx.x;
    if (i >= n * C) return;
    int r = i / C, c = i - r * C;
    float v = dis[r] * (t[i] + z[i]) + b[c];
    if (act == ACT_RELU) v = fmaxf(v, 0.f);
    else if (act == ACT_SIGM) v = 1.f / (1.f + expf(-v));
    out[i] = v;
}

__global__ void k_add_diag(float* __restrict__ A, int n) {
    int i = blockIdx.x * blockDim.x + threadIdx.x;
    if (i < n) A[(size_t)i * n + i] += 1.0f;
}
__global__ void k_zero_diag(float* __restrict__ A, int n) {
    int i = blockIdx.x * blockDim.x + threadIdx.x;
    if (i < n) A[(size_t)i * n + i] = 0.0f;
}

__global__ void k_pnorm(const float* __restrict__ p, int n, float* __restrict__ out) {
    __shared__ float red[256];
    float s = 0.f;
    for (int i = threadIdx.x; i < n; i += 256) s += p[i] * p[i];
    red[threadIdx.x] = s;
    __syncthreads();
    for (int o = 128; o > 0; o >>= 1) {
        if (threadIdx.x < o) red[threadIdx.x] += red[threadIdx.x + o];
        __syncthreads();
    }
    if (threadIdx.x == 0) out[0] = sqrtf(red[0]);
}

// score[i] = tanh(dot(h[i], p) / ||p||), one warp per row
__global__ void k_scores(const float* __restrict__ h, int n, int C,
                         const float* __restrict__ p, const float* __restrict__ pn,
                         float* __restrict__ score) {
    int row = blockIdx.x * 8 + (threadIdx.x >> 5);
    int lane = threadIdx.x & 31;
    if (row >= n) return;
    const float* hr = h + (size_t)row * C;
    float s = 0.f;
    for (int c = lane; c < C; c += 32) s += hr[c] * p[c];
    for (int o = 16; o > 0; o >>= 1) s += __shfl_xor_sync(0xffffffffu, s, o);
    if (lane == 0) score[row] = tanhf(s / pn[0]);
}

// single-block bitonic sort (descending) of (score, idx); write first k indices
__global__ void __launch_bounds__(1024) k_sort_topk(const float* __restrict__ score,
                                                    int n, int npad, int k,
                                                    int* __restrict__ perm) {
    __shared__ float skey[4096];
    __shared__ int   sidx[4096];
    for (int i = threadIdx.x; i < npad; i += blockDim.x) {
        skey[i] = (i < n) ? score[i] : -INFINITY;
        sidx[i] = i;
    }
    __syncthreads();
    for (int kk = 2; kk <= npad; kk <<= 1) {
        for (int j = kk >> 1; j > 0; j >>= 1) {
            for (int i = threadIdx.x; i < npad; i += blockDim.x) {
                int ixj = i ^ j;
                if (ixj > i) {
                    float a = skey[i], b = skey[ixj];
                    bool sw = ((i & kk) == 0) ? (a < b) : (a > b);  // descending
                    if (sw) {
                        skey[i] = b; skey[ixj] = a;
                        int t = sidx[i]; sidx[i] = sidx[ixj]; sidx[ixj] = t;
                    }
                }
            }
            __syncthreads();
        }
    }
    for (int i = threadIdx.x; i < k; i += blockDim.x) perm[i] = sidx[i];
}

__global__ void k_gatherX(const float* __restrict__ h, int C,
                          const int* __restrict__ perm, const float* __restrict__ score,
                          int k, float* __restrict__ out) {
    int i = blockIdx.x * blockDim.x + threadIdx.x;
    if (i >= k * C) return;
    int r = i / C, c = i - r * C;
    int pr = perm[r];
    out[i] = h[(size_t)pr * C + c] * score[pr];
}

__global__ void k_gatherA(const float* __restrict__ Asrc, int nsrc,
                          const int* __restrict__ perm, int k, float* __restrict__ Adst) {
    int c = blockIdx.x * blockDim.x + threadIdx.x;
    int r = blockIdx.y;
    if (c < k) Adst[(size_t)r * k + c] = Asrc[(size_t)perm[r] * nsrc + perm[c]];
}

// u[perm[r], :] += h[r, :]   (perm entries unique -> race-free)
__global__ void k_scatter_add(float* __restrict__ u, const float* __restrict__ h,
                              const int* __restrict__ perm, int k, int C) {
    int i = blockIdx.x * blockDim.x + threadIdx.x;
    if (i >= k * C) return;
    int r = i / C, c = i - r * C;
    u[(size_t)perm[r] * C + c] += h[i];
}

// ---------------- host orchestration ----------------
static void run_gemm(int M, int N, int K, const float* A, const float* B, float* C) {
    dim3 g((N + 127) / 128, (M + 127) / 128);
    sgemm<<<g, 256>>>(M, N, K, A, B, C);
}

// out = act( D^-1/2 (A+I) D^-1/2 (X @ W) + b )   without materializing An
static void run_gcn(const float* A, int n, const float* X, int inC,
                    const float* W, int outC, const float* b, float* out, int act,
                    float* xw, float* z, float* t, float* dis) {
    run_gemm(n, outC, inC, X, W, xw);
    k_dis<<<n, 256>>>(A, n, dis);
    int nc = n * outC;
    k_scale<<<(nc + 255) / 256, 256>>>(xw, dis, n, outC, z);
    run_gemm(n, outC, n, A, z, t);
    k_epilogue<<<(nc + 255) / 256, 256>>>(t, z, dis, b, n, outC, out, act);
}

// Aug = ((A+I)@(A+I)) with zeroed diagonal
static void run_augment(const float* A, int n, float* ApI, float* Aug) {
    cudaMemcpyAsync(ApI, A, (size_t)n * n * sizeof(float), cudaMemcpyDeviceToDevice, 0);
    k_add_diag<<<(n + 255) / 256, 256>>>(ApI, n);
    run_gemm(n, n, n, ApI, ApI, Aug);
    k_zero_diag<<<(n + 255) / 256, 256>>>(Aug, n);
}

static void run_pool(const float* h, int n, int npad, const float* p, int k,
                     const float* Aug, int* perm, float* xk, float* Ak,
                     float* score, float* pn) {
    k_pnorm<<<1, 256>>>(p, HC, pn);
    k_scores<<<(n + 7) / 8, 256>>>(h, n, HC, p, pn, score);
    k_sort_topk<<<1, 1024>>>(score, n, npad, k, perm);
    k_gatherX<<<(k * HC + 255) / 256, 256>>>(h, HC, perm, score, k, xk);
    dim3 ga((k + 255) / 256, k);
    k_gatherA<<<ga, 256>>>(Aug, n, perm, k, Ak);
}

extern "C" void kernel_launch(void* const* d_in, const int* in_sizes, int n_in,
                              void* d_out, int out_size) {
    const float* x   = (const float*)d_in[0];
    const int*   ei  = (const int*)  d_in[1];
    const float* Wd0 = (const float*)d_in[2];  const float* bd0 = (const float*)d_in[3];
    const float* Wd1 = (const float*)d_in[4];  const float* bd1 = (const float*)d_in[5];
    const float* Wd2 = (const float*)d_in[6];  const float* bd2 = (const float*)d_in[7];
    const float* Wd3 = (const float*)d_in[8];  const float* bd3 = (const float*)d_in[9];
    const float* p1  = (const float*)d_in[10];
    const float* p2  = (const float*)d_in[11];
    const float* p3  = (const float*)d_in[12];
    const float* Wu0 = (const float*)d_in[13]; const float* bu0 = (const float*)d_in[14];
    const float* Wu1 = (const float*)d_in[15]; const float* bu1 = (const float*)d_in[16];
    const float* Wu2 = (const float*)d_in[17]; const float* bu2 = (const float*)d_in[18];
    const int E = in_sizes[1] / 2;

    float *A0, *ApI, *Aug, *A1, *A2, *A3, *h0, *h1, *h2, *h3, *hb;
    float *xw, *z, *t, *u, *dis, *sc, *pn;
    int *pm0, *pm1, *pm2;
    cudaGetSymbolAddress((void**)&A0,  g_A0);
    cudaGetSymbolAddress((void**)&ApI, g_ApI);
    cudaGetSymbolAddress((void**)&Aug, g_Aug);
    cudaGetSymbolAddress((void**)&A1,  g_A1);
    cudaGetSymbolAddress((void**)&A2,  g_A2);
    cudaGetSymbolAddress((void**)&A3,  g_A3);
    cudaGetSymbolAddress((void**)&h0,  g_h0);
    cudaGetSymbolAddress((void**)&h1,  g_h1);
    cudaGetSymbolAddress((void**)&h2,  g_h2);
    cudaGetSymbolAddress((void**)&h3,  g_h3);
    cudaGetSymbolAddress((void**)&hb,  g_hb);
    cudaGetSymbolAddress((void**)&xw,  g_xw);
    cudaGetSymbolAddress((void**)&z,   g_z);
    cudaGetSymbolAddress((void**)&t,   g_t);
    cudaGetSymbolAddress((void**)&u,   g_u);
    cudaGetSymbolAddress((void**)&dis, g_dis);
    cudaGetSymbolAddress((void**)&sc,  g_sc);
    cudaGetSymbolAddress((void**)&pn,  g_pn);
    cudaGetSymbolAddress((void**)&pm0, g_perm0);
    cudaGetSymbolAddress((void**)&pm1, g_perm1);
    cudaGetSymbolAddress((void**)&pm2, g_perm2);

    // ---- build dense adjacency ----
    cudaMemsetAsync(A0, 0, (size_t)N0 * N0 * sizeof(float), 0);
    k_edges<<<(E + 255) / 256, 256>>>(ei, E, A0);

    // ---- down path ----
    run_gcn(A0, N0, x, INC, Wd0, HC, bd0, h0, ACT_RELU, xw, z, t, dis);

    run_augment(A0, N0, ApI, Aug);
    run_pool(h0, N0, 4096, p1, KP1, Aug, pm0, u, A1, sc, pn);
    run_gcn(A1, KP1, u, HC, Wd1, HC, bd1, h1, ACT_RELU, xw, z, t, dis);

    run_augment(A1, KP1, ApI, Aug);
    run_pool(h1, KP1, 2048, p2, KP2, Aug, pm1, u, A2, sc, pn);
    run_gcn(A2, KP2, u, HC, Wd2, HC, bd2, h2, ACT_RELU, xw, z, t, dis);

    run_augment(A2, KP2, ApI, Aug);
    run_pool(h2, KP2, 1024, p3, KP3, Aug, pm2, u, A3, sc, pn);
    run_gcn(A3, KP3, u, HC, Wd3, HC, bd3, h3, ACT_RELU, xw, z, t, dis);

    // ---- up path ----
    // i=0 (j=2): res=h2 (1000), unpool h3 via perm2, gcn(A2, Wu0) + relu
    cudaMemcpyAsync(u, h2, (size_t)KP2 * HC * sizeof(float), cudaMemcpyDeviceToDevice, 0);
    k_scatter_add<<<(KP3 * HC + 255) / 256, 256>>>(u, h3, pm2, KP3, HC);
    run_gcn(A2, KP2, u, HC, Wu0, HC, bu0, hb, ACT_RELU, xw, z, t, dis);

    // i=1 (j=1): res=h1 (2000), unpool hb via perm1, gcn(A1, Wu1) + relu
    cudaMemcpyAsync(u, h1, (size_t)KP1 * HC * sizeof(float), cudaMemcpyDeviceToDevice, 0);
    k_scatter_add<<<(KP2 * HC + 255) / 256, 256>>>(u, hb, pm1, KP2, HC);
    run_gcn(A1, KP1, u, HC, Wu1, HC, bu1, hb, ACT_RELU, xw, z, t, dis);

    // i=2 (j=0): res=h0 (4096), unpool hb via perm0, gcn(A0, Wu2) + sigmoid -> out
    cudaMemcpyAsync(u, h0, (size_t)N0 * HC * sizeof(float), cudaMemcpyDeviceToDevice, 0);
    k_scatter_add<<<(KP1 * HC + 255) / 256, 256>>>(u, hb, pm0, KP1, HC);
    run_gcn(A0, N0, u, HC, Wu2, OC, bu2, (float*)d_out, ACT_SIGM, xw, z, t, dis);
}

// round 3
// speedup vs baseline: 1.8500x; 1.8500x over previous
#include <cuda_runtime.h>
#include <cuda_bf16.h>
#include <cstdint>
#include <math.h>

// ---------------- problem constants ----------------
#define N0   4096
#define INC  128
#define HC   512
#define OC   64
#define KP1  2000
#define KP2  1000
#define KP3  500

#define ACT_NONE 0
#define ACT_RELU 1
#define ACT_SIGM 2

// ---------------- scratch (device globals; allocation-free) ----------------
__device__ float g_A0 [(size_t)N0*N0];      // 64 MB  level-0 adjacency
__device__ float g_Aug[(size_t)N0*N0];      // 64 MB  augmented adjacency (padded ld)
__device__ float g_A1 [(size_t)KP1*KP1];
__device__ float g_A2 [(size_t)KP2*KP2];
__device__ float g_A3 [(size_t)KP3*KP3];
__device__ float g_h0 [(size_t)N0*HC];
__device__ float g_h1 [(size_t)KP1*HC];
__device__ float g_h2 [(size_t)KP2*HC];
__device__ float g_h3 [(size_t)KP3*HC];
__device__ float g_hb [(size_t)KP1*HC];
__device__ float g_xw [(size_t)N0*HC];
__device__ float g_z  [(size_t)N0*HC];
__device__ float g_t  [(size_t)N0*HC];
__device__ float g_u  [(size_t)N0*HC];
__device__ float g_dis[N0];
__device__ float g_sc [N0];
__device__ float g_pn [1];
__device__ int   g_perm0[KP1];
__device__ int   g_perm1[KP2];
__device__ int   g_perm2[KP3];
// bf16 tensor-core operands
__device__ __nv_bfloat16 g_bA [(size_t)4096*4096];  // 32 MB  (A+I) bf16, padded
__device__ __nv_bfloat16 g_bX [(size_t)1024*2048];  // level-3 split [hi|lo]
__device__ __nv_bfloat16 g_bY1[(size_t)2048*1024];  // [hi;lo]
__device__ __nv_bfloat16 g_bY2[(size_t)2048*1024];  // [lo;hi]

// ---------------- bf16 tensor-core GEMM ----------------
// C(MxN fp32) = A(MxK bf16,row) @ B(KxN bf16,row); M,N mult of 128, K mult of 32
// (operands pre-padded with zeros). acc=1 -> C += A@B.
__global__ void __launch_bounds__(256) hgemm(int M, int N, int K,
        const __nv_bfloat16* __restrict__ A, int lda,
        const __nv_bfloat16* __restrict__ B, int ldb,
        float* __restrict__ C, int ldc, int acc) {
    __shared__ __nv_bfloat16 As[128][40];   // pad 40 -> conflict-free ldmatrix
    __shared__ __nv_bfloat16 Bs[32][136];
    const int tid  = threadIdx.x;
    const int lane = tid & 31;
    const int warp = tid >> 5;
    const int wm = (warp >> 2) * 64;   // 2 warp rows (64 M each)
    const int wn = (warp & 3) * 32;    // 4 warp cols (32 N each)
    const int m0 = blockIdx.y * 128;
    const int n0 = blockIdx.x * 128;

    float c[4][4][4];
#pragma unroll
    for (int mt = 0; mt < 4; mt++)
#pragma unroll
        for (int nt = 0; nt < 4; nt++)
#pragma unroll
            for (int r = 0; r < 4; r++) c[mt][nt][r] = 0.f;

    const int ar = tid >> 1, ac = (tid & 1) * 16;   // A tile 128x32: 16 halves/thread
    const int br = tid >> 3, bc = (tid & 7) * 16;   // B tile 32x128

    for (int kk = 0; kk < K; kk += 32) {
        const uint4* ag = reinterpret_cast<const uint4*>(A + (size_t)(m0 + ar) * lda + kk + ac);
        uint4 av0 = ag[0], av1 = ag[1];
        *reinterpret_cast<uint4*>(&As[ar][ac])     = av0;
        *reinterpret_cast<uint4*>(&As[ar][ac + 8]) = av1;
        const uint4* bg = reinterpret_cast<const uint4*>(B + (size_t)(kk + br) * ldb + n0 + bc);
        uint4 bv0 = bg[0], bv1 = bg[1];
        *reinterpret_cast<uint4*>(&Bs[br][bc])     = bv0;
        *reinterpret_cast<uint4*>(&Bs[br][bc + 8]) = bv1;
        __syncthreads();

#pragma unroll
        for (int ks = 0; ks < 32; ks += 16) {
            uint32_t af[4][4];
#pragma unroll
            for (int mt = 0; mt < 4; mt++) {
                unsigned addr = (unsigned)__cvta_generic_to_shared(
                    &As[wm + mt * 16 + (lane & 15)][ks + (lane >> 4) * 8]);
                asm volatile("ldmatrix.sync.aligned.m8n8.x4.shared.b16 {%0,%1,%2,%3}, [%4];"
                    : "=r"(af[mt][0]), "=r"(af[mt][1]), "=r"(af[mt][2]), "=r"(af[mt][3])
                    : "r"(addr));
            }
            uint32_t bfr[4][2];
#pragma unroll
            for (int nt = 0; nt < 4; nt++) {
                unsigned addr = (unsigned)__cvta_generic_to_shared(
                    &Bs[ks + (lane & 15)][wn + nt * 8]);
                asm volatile("ldmatrix.sync.aligned.m8n8.x2.trans.shared.b16 {%0,%1}, [%2];"
                    : "=r"(bfr[nt][0]), "=r"(bfr[nt][1]) : "r"(addr));
            }
#pragma unroll
            for (int mt = 0; mt < 4; mt++)
#pragma unroll
                for (int nt = 0; nt < 4; nt++)
                    asm volatile(
                        "mma.sync.aligned.m16n8k16.row.col.f32.bf16.bf16.f32 "
                        "{%0,%1,%2,%3}, {%4,%5,%6,%7}, {%8,%9}, {%0,%1,%2,%3};"
                        : "+f"(c[mt][nt][0]), "+f"(c[mt][nt][1]),
                          "+f"(c[mt][nt][2]), "+f"(c[mt][nt][3])
                        : "r"(af[mt][0]), "r"(af[mt][1]), "r"(af[mt][2]), "r"(af[mt][3]),
                          "r"(bfr[nt][0]), "r"(bfr[nt][1]));
        }
        __syncthreads();
    }

    const int r0 = lane >> 2, c0 = (lane & 3) * 2;
#pragma unroll
    for (int mt = 0; mt < 4; mt++)
#pragma unroll
        for (int nt = 0; nt < 4; nt++) {
            int row = m0 + wm + mt * 16 + r0;
            int col = n0 + wn + nt * 8 + c0;
            float* p0 = C + (size_t)row * ldc + col;
            float* p1 = C + (size_t)(row + 8) * ldc + col;
            if (acc) {
                p0[0] += c[mt][nt][0]; p0[1] += c[mt][nt][1];
                p1[0] += c[mt][nt][2]; p1[1] += c[mt][nt][3];
            } else {
                p0[0] = c[mt][nt][0]; p0[1] = c[mt][nt][1];
                p1[0] = c[mt][nt][2]; p1[1] = c[mt][nt][3];
            }
        }
}

// ---------------- SGEMM (fp32 SIMT) for GCN path ----------------
__global__ void __launch_bounds__(256) sgemm(int M, int N, int K,
                                             const float* __restrict__ A,
                                             const float* __restrict__ B,
                                             float* __restrict__ C) {
    __shared__ float As[8][128];
    __shared__ float Bs[8][128];
    const int tid  = threadIdx.x;
    const int tx   = tid & 15;
    const int ty   = tid >> 4;
    const int row0 = blockIdx.y * 128;
    const int col0 = blockIdx.x * 128;
    const int a_row = tid >> 1, a_col = (tid & 1) << 2;
    const int b_row = tid >> 5, b_col = (tid & 31) << 2;

    float acc[8][8];
#pragma unroll
    for (int i = 0; i < 8; i++)
#pragma unroll
        for (int j = 0; j < 8; j++) acc[i][j] = 0.f;

    for (int kk = 0; kk < K; kk += 8) {
        float4 av = make_float4(0.f, 0.f, 0.f, 0.f);
        {
            int gm = row0 + a_row, gk = kk + a_col;
            if (gm < M && gk < K)
                av = *reinterpret_cast<const float4*>(A + (size_t)gm * K + gk);
        }
        As[a_col + 0][a_row] = av.x;
        As[a_col + 1][a_row] = av.y;
        As[a_col + 2][a_row] = av.z;
        As[a_col + 3][a_row] = av.w;

        float4 bv = make_float4(0.f, 0.f, 0.f, 0.f);
        {
            int gk = kk + b_row, gn = col0 + b_col;
            if (gk < K && gn < N)
                bv = *reinterpret_cast<const float4*>(B + (size_t)gk * N + gn);
        }
        *reinterpret_cast<float4*>(&Bs[b_row][b_col]) = bv;
        __syncthreads();

#pragma unroll
        for (int k = 0; k < 8; k++) {
            float4 a0 = *reinterpret_cast<const float4*>(&As[k][ty * 8]);
            float4 a1 = *reinterpret_cast<const float4*>(&As[k][ty * 8 + 4]);
            float4 b0 = *reinterpret_cast<const float4*>(&Bs[k][tx * 8]);
            float4 b1 = *reinterpret_cast<const float4*>(&Bs[k][tx * 8 + 4]);
            float a[8] = {a0.x, a0.y, a0.z, a0.w, a1.x, a1.y, a1.z, a1.w};
            float b[8] = {b0.x, b0.y, b0.z, b0.w, b1.x, b1.y, b1.z, b1.w};
#pragma unroll
            for (int i = 0; i < 8; i++)
#pragma unroll
                for (int j = 0; j < 8; j++) acc[i][j] += a[i] * b[j];
        }
        __syncthreads();
    }

#pragma unroll
    for (int i = 0; i < 8; i++) {
        int gm = row0 + ty * 8 + i;
        if (gm >= M) continue;
        float* Cr = C + (size_t)gm * N;
#pragma unroll
        for (int j = 0; j < 8; j++) {
            int gn = col0 + tx * 8 + j;
            if (gn < N) Cr[gn] = acc[i][j];
        }
    }
}

// ---------------- elementwise / graph kernels ----------------
__global__ void k_edges(const int* __restrict__ ei, int E, float* __restrict__ A) {
    int e = blockIdx.x * blockDim.x + threadIdx.x;
    if (e >= E) return;
    int s = ei[e], d = ei[E + e];
    A[(size_t)s * N0 + d] = 1.f;
    A[(size_t)d * N0 + s] = 1.f;
}

__global__ void k_dis(const float* __restrict__ A, int n, float* __restrict__ dis) {
    __shared__ float red[256];
    int row = blockIdx.x;
    const float* Ar = A + (size_t)row * n;
    float s = 0.f;
    for (int j = threadIdx.x; j < n; j += 256) s += Ar[j];
    red[threadIdx.x] = s;
    __syncthreads();
    for (int o = 128; o > 0; o >>= 1) {
        if (threadIdx.x < o) red[threadIdx.x] += red[threadIdx.x + o];
        __syncthreads();
    }
    if (threadIdx.x == 0) dis[row] = rsqrtf(red[0] + 1.0f);
}

__global__ void k_scale(const float* __restrict__ xw, const float* __restrict__ dis,
                        int n, int C, float* __restrict__ z) {
    int i = blockIdx.x * blockDim.x + threadIdx.x;
    if (i >= n * C) return;
    z[i] = dis[i / C] * xw[i];
}

__global__ void k_epilogue(const float* __restrict__ t, const float* __restrict__ z,
                           const float* __restrict__ dis, const float* __restrict__ b,
                           int n, int C, float* __restrict__ out, int act) {
    int i = blockIdx.x * blockDim.x + threadIdx.x;
    if (i >= n * C) return;
    int r = i / C, c = i - r * C;
    float v = dis[r] * (t[i] + z[i]) + b[c];
    if (act == ACT_RELU) v = fmaxf(v, 0.f);
    else if (act == ACT_SIGM) v = 1.f / (1.f + expf(-v));
    out[i] = v;
}

// bf16(A+I), zero-padded to np x np
__global__ void k_tobf16_adj(const float* __restrict__ A, int n, int np,
                             __nv_bfloat16* __restrict__ out) {
    int i = blockIdx.x * blockDim.x + threadIdx.x;
    if (i >= np * np) return;
    int r = i / np, c = i - r * np;
    float v = 0.f;
    if (r < n && c < n) v = A[(size_t)r * n + c] + (r == c ? 1.f : 0.f);
    out[i] = __float2bfloat16(v);
}

// level-3 exact split pack: hi/lo of (A+I), into [hi|lo], [hi;lo], [lo;hi]
__global__ void k_split_pack(const float* __restrict__ A, int n, int np,
                             __nv_bfloat16* __restrict__ X,   // np x 2np
                             __nv_bfloat16* __restrict__ Y1,  // 2np x np
                             __nv_bfloat16* __restrict__ Y2) {
    int i = blockIdx.x * blockDim.x + threadIdx.x;
    if (i >= np * np) return;
    int r = i / np, c = i - r * np;
    float v = 0.f;
    if (r < n && c < n) v = A[(size_t)r * n + c] + (r == c ? 1.f : 0.f);
    __nv_bfloat16 hi = __float2bfloat16(v);
    __nv_bfloat16 lo = __float2bfloat16(v - __bfloat162float(hi));
    X[(size_t)r * (2 * np) + c]      = hi;
    X[(size_t)r * (2 * np) + np + c] = lo;
    Y1[(size_t)r * np + c]            = hi;
    Y1[(size_t)(np + r) * np + c]     = lo;
    Y2[(size_t)r * np + c]            = lo;
    Y2[(size_t)(np + r) * np + c]     = hi;
}

__global__ void k_zero_diag_ld(float* __restrict__ A, int n, int ld) {
    int i = blockIdx.x * blockDim.x + threadIdx.x;
    if (i < n) A[(size_t)i * ld + i] = 0.0f;
}

__global__ void k_pnorm(const float* __restrict__ p, int n, float* __restrict__ out) {
    __shared__ float red[256];
    float s = 0.f;
    for (int i = threadIdx.x; i < n; i += 256) s += p[i] * p[i];
    red[threadIdx.x] = s;
    __syncthreads();
    for (int o = 128; o > 0; o >>= 1) {
        if (threadIdx.x < o) red[threadIdx.x] += red[threadIdx.x + o];
        __syncthreads();
    }
    if (threadIdx.x == 0) out[0] = sqrtf(red[0]);
}

__global__ void k_scores(const float* __restrict__ h, int n, int C,
                         const float* __restrict__ p, const float* __restrict__ pn,
                         float* __restrict__ score) {
    int row = blockIdx.x * 8 + (threadIdx.x >> 5);
    int lane = threadIdx.x & 31;
    if (row >= n) return;
    const float* hr = h + (size_t)row * C;
    float s = 0.f;
    for (int c = lane; c < C; c += 32) s += hr[c] * p[c];
    for (int o = 16; o > 0; o >>= 1) s += __shfl_xor_sync(0xffffffffu, s, o);
    if (lane == 0) score[row] = tanhf(s / pn[0]);
}

__global__ void __launch_bounds__(1024) k_sort_topk(const float* __restrict__ score,
                                                    int n, int npad, int k,
                                                    int* __restrict__ perm) {
    __shared__ float skey[4096];
    __shared__ int   sidx[4096];
    for (int i = threadIdx.x; i < npad; i += blockDim.x) {
        skey[i] = (i < n) ? score[i] : -INFINITY;
        sidx[i] = i;
    }
    __syncthreads();
    for (int kk = 2; kk <= npad; kk <<= 1) {
        for (int j = kk >> 1; j > 0; j >>= 1) {
            for (int i = threadIdx.x; i < npad; i += blockDim.x) {
                int ixj = i ^ j;
                if (ixj > i) {
                    float a = skey[i], b = skey[ixj];
                    bool sw = ((i & kk) == 0) ? (a < b) : (a > b);
                    if (sw) {
                        skey[i] = b; skey[ixj] = a;
                        int t = sidx[i]; sidx[i] = sidx[ixj]; sidx[ixj] = t;
                    }
                }
            }
            __syncthreads();
        }
    }
    for (int i = threadIdx.x; i < k; i += blockDim.x) perm[i] = sidx[i];
}

__global__ void k_gatherX(const float* __restrict__ h, int C,
                          const int* __restrict__ perm, const float* __restrict__ score,
                          int k, float* __restrict__ out) {
    int i = blockIdx.x * blockDim.x + threadIdx.x;
    if (i >= k * C) return;
    int r = i / C, c = i - r * C;
    int pr = perm[r];
    out[i] = h[(size_t)pr * C + c] * score[pr];
}

__global__ void k_gatherA(const float* __restrict__ Asrc, int srcld,
                          const int* __restrict__ perm, int k, float* __restrict__ Adst) {
    int c = blockIdx.x * blockDim.x + threadIdx.x;
    int r = blockIdx.y;
    if (c < k) Adst[(size_t)r * k + c] = Asrc[(size_t)perm[r] * srcld + perm[c]];
}

__global__ void k_scatter_add(float* __restrict__ u, const float* __restrict__ h,
                              const int* __restrict__ perm, int k, int C) {
    int i = blockIdx.x * blockDim.x + threadIdx.x;
    if (i >= k * C) return;
    int r = i / C, c = i - r * C;
    u[(size_t)perm[r] * C + c] += h[i];
}

// ---------------- host orchestration ----------------
static void run_gemm(int M, int N, int K, const float* A, const float* B, float* C) {
    dim3 g((N + 127) / 128, (M + 127) / 128);
    sgemm<<<g, 256>>>(M, N, K, A, B, C);
}

static void run_hgemm(int M, int N, int K, const __nv_bfloat16* A, int lda,
                      const __nv_bfloat16* B, int ldb, float* C, int ldc, int acc) {
    dim3 g(N / 128, M / 128);
    hgemm<<<g, 256>>>(M, N, K, A, lda, B, ldb, C, ldc, acc);
}

static void run_gcn(const float* A, int n, const float* X, int inC,
                    const float* W, int outC, const float* b, float* out, int act,
                    float* xw, float* z, float* t, float* dis) {
    run_gemm(n, outC, inC, X, W, xw);
    k_dis<<<n, 256>>>(A, n, dis);
    int nc = n * outC;
    k_scale<<<(nc + 255) / 256, 256>>>(xw, dis, n, outC, z);
    run_gemm(n, outC, n, A, z, t);
    k_epilogue<<<(nc + 255) / 256, 256>>>(t, z, dis, b, n, outC, out, act);
}

// Aug(ld=np) = ((A+I)@(A+I)), diag zeroed. Exact: entries of A+I are small ints.
static void run_augment_tc(const float* A, int n, int np, __nv_bfloat16* bA, float* Aug) {
    int tot = np * np;
    k_tobf16_adj<<<(tot + 255) / 256, 256>>>(A, n, np, bA);
    run_hgemm(np, np, np, bA, np, bA, np, Aug, np, 0);
    k_zero_diag_ld<<<(n + 255) / 256, 256>>>(Aug, n, np);
}

// exact split augment for possibly-large integer entries (level 3)
static void run_augment_split(const float* A, int n, int np,
                              __nv_bfloat16* bX, __nv_bfloat16* bY1, __nv_bfloat16* bY2,
                              float* Aug) {
    int tot = np * np;
    k_split_pack<<<(tot + 255) / 256, 256>>>(A, n, np, bX, bY1, bY2);
    run_hgemm(np, np, 2 * np, bX, 2 * np, bY1, np, Aug, np, 0);
    run_hgemm(np, np, 2 * np, bX, 2 * np, bY2, np, Aug, np, 1);
    k_zero_diag_ld<<<(n + 255) / 256, 256>>>(Aug, n, np);
}

static void run_pool(const float* h, int n, int npad, const float* p, int k,
                     const float* Aug, int augld, int* perm, float* xk, float* Ak,
                     float* score, float* pn) {
    k_pnorm<<<1, 256>>>(p, HC, pn);
    k_scores<<<(n + 7) / 8, 256>>>(h, n, HC, p, pn, score);
    k_sort_topk<<<1, 1024>>>(score, n, npad, k, perm);
    k_gatherX<<<(k * HC + 255) / 256, 256>>>(h, HC, perm, score, k, xk);
    dim3 ga((k + 255) / 256, k);
    k_gatherA<<<ga, 256>>>(Aug, augld, perm, k, Ak);
}

extern "C" void kernel_launch(void* const* d_in, const int* in_sizes, int n_in,
                              void* d_out, int out_size) {
    const float* x   = (const float*)d_in[0];
    const int*   ei  = (const int*)  d_in[1];
    const float* Wd0 = (const float*)d_in[2];  const float* bd0 = (const float*)d_in[3];
    const float* Wd1 = (const float*)d_in[4];  const float* bd1 = (const float*)d_in[5];
    const float* Wd2 = (const float*)d_in[6];  const float* bd2 = (const float*)d_in[7];
    const float* Wd3 = (const float*)d_in[8];  const float* bd3 = (const float*)d_in[9];
    const float* p1  = (const float*)d_in[10];
    const float* p2  = (const float*)d_in[11];
    const float* p3  = (const float*)d_in[12];
    const float* Wu0 = (const float*)d_in[13]; const float* bu0 = (const float*)d_in[14];
    const float* Wu1 = (const float*)d_in[15]; const float* bu1 = (const float*)d_in[16];
    const float* Wu2 = (const float*)d_in[17]; const float* bu2 = (const float*)d_in[18];
    const int E = in_sizes[1] / 2;

    float *A0, *Aug, *A1, *A2, *A3, *h0, *h1, *h2, *h3, *hb;
    float *xw, *z, *t, *u, *dis, *sc, *pn;
    int *pm0, *pm1, *pm2;
    __nv_bfloat16 *bA, *bX, *bY1, *bY2;
    cudaGetSymbolAddress((void**)&A0,  g_A0);
    cudaGetSymbolAddress((void**)&Aug, g_Aug);
    cudaGetSymbolAddress((void**)&A1,  g_A1);
    cudaGetSymbolAddress((void**)&A2,  g_A2);
    cudaGetSymbolAddress((void**)&A3,  g_A3);
    cudaGetSymbolAddress((void**)&h0,  g_h0);
    cudaGetSymbolAddress((void**)&h1,  g_h1);
    cudaGetSymbolAddress((void**)&h2,  g_h2);
    cudaGetSymbolAddress((void**)&h3,  g_h3);
    cudaGetSymbolAddress((void**)&hb,  g_hb);
    cudaGetSymbolAddress((void**)&xw,  g_xw);
    cudaGetSymbolAddress((void**)&z,   g_z);
    cudaGetSymbolAddress((void**)&t,   g_t);
    cudaGetSymbolAddress((void**)&u,   g_u);
    cudaGetSymbolAddress((void**)&dis, g_dis);
    cudaGetSymbolAddress((void**)&sc,  g_sc);
    cudaGetSymbolAddress((void**)&pn,  g_pn);
    cudaGetSymbolAddress((void**)&pm0, g_perm0);
    cudaGetSymbolAddress((void**)&pm1, g_perm1);
    cudaGetSymbolAddress((void**)&pm2, g_perm2);
    cudaGetSymbolAddress((void**)&bA,  g_bA);
    cudaGetSymbolAddress((void**)&bX,  g_bX);
    cudaGetSymbolAddress((void**)&bY1, g_bY1);
    cudaGetSymbolAddress((void**)&bY2, g_bY2);

    // ---- build dense adjacency ----
    cudaMemsetAsync(A0, 0, (size_t)N0 * N0 * sizeof(float), 0);
    k_edges<<<(E + 255) / 256, 256>>>(ei, E, A0);

    // ---- down path ----
    run_gcn(A0, N0, x, INC, Wd0, HC, bd0, h0, ACT_RELU, xw, z, t, dis);

    run_augment_tc(A0, N0, 4096, bA, Aug);                       // exact: entries {0,1,2}
    run_pool(h0, N0, 4096, p1, KP1, Aug, 4096, pm0, u, A1, sc, pn);
    run_gcn(A1, KP1, u, HC, Wd1, HC, bd1, h1, ACT_RELU, xw, z, t, dis);

    run_augment_tc(A1, KP1, 2048, bA, Aug);                      // exact: small int entries
    run_pool(h1, KP1, 2048, p2, KP2, Aug, 2048, pm1, u, A2, sc, pn);
    run_gcn(A2, KP2, u, HC, Wd2, HC, bd2, h2, ACT_RELU, xw, z, t, dis);

    run_augment_split(A2, KP2, 1024, bX, bY1, bY2, Aug);         // exact hi/lo split
    run_pool(h2, KP2, 1024, p3, KP3, Aug, 1024, pm2, u, A3, sc, pn);
    run_gcn(A3, KP3, u, HC, Wd3, HC, bd3, h3, ACT_RELU, xw, z, t, dis);

    // ---- up path ----
    cudaMemcpyAsync(u, h2, (size_t)KP2 * HC * sizeof(float), cudaMemcpyDeviceToDevice, 0);
    k_scatter_add<<<(KP3 * HC + 255) / 256, 256>>>(u, h3, pm2, KP3, HC);
    run_gcn(A2, KP2, u, HC, Wu0, HC, bu0, hb, ACT_RELU, xw, z, t, dis);

    cudaMemcpyAsync(u, h1, (size_t)KP1 * HC * sizeof(float), cudaMemcpyDeviceToDevice, 0);
    k_scatter_add<<<(KP2 * HC + 255) / 256, 256>>>(u, hb, pm1, KP2, HC);
    run_gcn(A1, KP1, u, HC, Wu1, HC, bu1, hb, ACT_RELU, xw, z, t, dis);

    cudaMemcpyAsync(u, h0, (size_t)N0 * HC * sizeof(float), cudaMemcpyDeviceToDevice, 0);
    k_scatter_add<<<(KP1 * HC + 255) / 256, 256>>>(u, hb, pm0, KP1, HC);
    run_gcn(A0, N0, u, HC, Wu2, OC, bu2, (float*)d_out, ACT_SIGM, xw, z, t, dis);
}

// round 4
// speedup vs baseline: 3.0016x; 1.6225x over previous
#include <cuda_runtime.h>
#include <cuda_bf16.h>
#include <cstdint>
#include <math.h>

// ---------------- problem constants ----------------
#define N0   4096
#define INC  128
#define HC   512
#define OC   64
#define KP1  2000
#define KP2  1000
#define KP3  500

#define ACT_NONE 0
#define ACT_RELU 1
#define ACT_SIGM 2

// ---------------- scratch (device globals; allocation-free) ----------------
__device__ float g_A0 [(size_t)N0*N0];      // fp32 adjacencies (for deg rowsums + gathers)
__device__ float g_Aug[(size_t)N0*N0];      // augmented adjacency (padded ld)
__device__ float g_A1 [(size_t)KP1*KP1];
__device__ float g_A2 [(size_t)KP2*KP2];
__device__ float g_A3 [(size_t)KP3*KP3];
__device__ float g_h0 [(size_t)N0*HC];
__device__ float g_h1 [(size_t)KP1*HC];
__device__ float g_h2 [(size_t)KP2*HC];
__device__ float g_h3 [(size_t)KP3*HC];
__device__ float g_hb [(size_t)KP1*HC];
__device__ float g_xw [(size_t)N0*HC];
__device__ float g_t  [(size_t)N0*HC];
__device__ float g_u  [(size_t)N0*HC];
__device__ float g_dis[N0];
__device__ float g_sc [N0];
__device__ float g_pn [1];
__device__ int   g_perm0[KP1];
__device__ int   g_perm1[KP2];
__device__ int   g_perm2[KP3];
// bf16 tensor-core operands
__device__ __nv_bfloat16 g_bA0 [(size_t)4096*4096];  // bf16(A0+I) padded
__device__ __nv_bfloat16 g_bA1 [(size_t)2048*2048];  // bf16(A1+I) padded
__device__ __nv_bfloat16 g_bX2 [(size_t)1024*2048];  // (A2+I) split [hi|lo]
__device__ __nv_bfloat16 g_bX3 [(size_t)512*1024];   // (A3+I) split [hi|lo]
__device__ __nv_bfloat16 g_bY1 [(size_t)2048*1024];  // augment2 temp [hi;lo]
__device__ __nv_bfloat16 g_bY2 [(size_t)2048*1024];  // augment2 temp [lo;hi]
__device__ __nv_bfloat16 g_bzh [(size_t)4096*512];   // z hi
__device__ __nv_bfloat16 g_bzl [(size_t)4096*512];   // z lo
__device__ __nv_bfloat16 g_bzs1[(size_t)2048*512];   // [zh;zl]
__device__ __nv_bfloat16 g_bzs2[(size_t)2048*512];   // [zl;zh]

// ---------------- cp.async helpers ----------------
#define CPASYNC16(dst_u32, src_ptr) \
    asm volatile("cp.async.ca.shared.global [%0], [%1], 16;" :: "r"(dst_u32), "l"(src_ptr))
#define CP_COMMIT() asm volatile("cp.async.commit_group;")

// ---------------- bf16 tensor-core GEMM (2-stage cp.async pipeline) ----------------
// C(MxN fp32) = A(MxK bf16,row,lda) @ B(KxN bf16,row,ldb); M,N mult of 128, K mult of 32.
__global__ void __launch_bounds__(256) hgemm(int M, int N, int K,
        const __nv_bfloat16* __restrict__ A, int lda,
        const __nv_bfloat16* __restrict__ B, int ldb,
        float* __restrict__ C, int ldc, int acc) {
    __shared__ __nv_bfloat16 As[2][128][40];
    __shared__ __nv_bfloat16 Bs[2][32][136];
    const int tid  = threadIdx.x;
    const int lane = tid & 31;
    const int warp = tid >> 5;
    const int wm = (warp >> 2) * 64;
    const int wn = (warp & 3) * 32;
    const int m0 = blockIdx.y * 128;
    const int n0 = blockIdx.x * 128;

    const int ar = tid >> 1, ac = (tid & 1) * 16;
    const int br = tid >> 3, bc = (tid & 7) * 16;

    float c[4][4][4];
#pragma unroll
    for (int mt = 0; mt < 4; mt++)
#pragma unroll
        for (int nt = 0; nt < 4; nt++)
#pragma unroll
            for (int r = 0; r < 4; r++) c[mt][nt][r] = 0.f;

    const int ntile = K >> 5;

    // prologue: stage 0
    {
        unsigned da = (unsigned)__cvta_generic_to_shared(&As[0][ar][ac]);
        const __nv_bfloat16* pa = A + (size_t)(m0 + ar) * lda + ac;
        CPASYNC16(da, pa);
        CPASYNC16(da + 16, pa + 8);
        unsigned db = (unsigned)__cvta_generic_to_shared(&Bs[0][br][bc]);
        const __nv_bfloat16* pb = B + (size_t)br * ldb + n0 + bc;
        CPASYNC16(db, pb);
        CPASYNC16(db + 16, pb + 8);
        CP_COMMIT();
    }

    for (int it = 0; it < ntile; ++it) {
        if (it + 1 < ntile) {
            int s = (it + 1) & 1, kk = (it + 1) << 5;
            unsigned da = (unsigned)__cvta_generic_to_shared(&As[s][ar][ac]);
            const __nv_bfloat16* pa = A + (size_t)(m0 + ar) * lda + kk + ac;
            CPASYNC16(da, pa);
            CPASYNC16(da + 16, pa + 8);
            unsigned db = (unsigned)__cvta_generic_to_shared(&Bs[s][br][bc]);
            const __nv_bfloat16* pb = B + (size_t)(kk + br) * ldb + n0 + bc;
            CPASYNC16(db, pb);
            CPASYNC16(db + 16, pb + 8);
            CP_COMMIT();
            asm volatile("cp.async.wait_group 1;");
        } else {
            asm volatile("cp.async.wait_group 0;");
        }
        __syncthreads();

        const int s = it & 1;
#pragma unroll
        for (int ks = 0; ks < 32; ks += 16) {
            uint32_t af[4][4];
#pragma unroll
            for (int mt = 0; mt < 4; mt++) {
                unsigned addr = (unsigned)__cvta_generic_to_shared(
                    &As[s][wm + mt * 16 + (lane & 15)][ks + (lane >> 4) * 8]);
                asm volatile("ldmatrix.sync.aligned.m8n8.x4.shared.b16 {%0,%1,%2,%3}, [%4];"
                    : "=r"(af[mt][0]), "=r"(af[mt][1]), "=r"(af[mt][2]), "=r"(af[mt][3])
                    : "r"(addr));
            }
            uint32_t bfr[4][2];
#pragma unroll
            for (int nt = 0; nt < 4; nt++) {
                unsigned addr = (unsigned)__cvta_generic_to_shared(
                    &Bs[s][ks + (lane & 15)][wn + nt * 8]);
                asm volatile("ldmatrix.sync.aligned.m8n8.x2.trans.shared.b16 {%0,%1}, [%2];"
                    : "=r"(bfr[nt][0]), "=r"(bfr[nt][1]) : "r"(addr));
            }
#pragma unroll
            for (int mt = 0; mt < 4; mt++)
#pragma unroll
                for (int nt = 0; nt < 4; nt++)
                    asm volatile(
                        "mma.sync.aligned.m16n8k16.row.col.f32.bf16.bf16.f32 "
                        "{%0,%1,%2,%3}, {%4,%5,%6,%7}, {%8,%9}, {%0,%1,%2,%3};"
                        : "+f"(c[mt][nt][0]), "+f"(c[mt][nt][1]),
                          "+f"(c[mt][nt][2]), "+f"(c[mt][nt][3])
                        : "r"(af[mt][0]), "r"(af[mt][1]), "r"(af[mt][2]), "r"(af[mt][3]),
                          "r"(bfr[nt][0]), "r"(bfr[nt][1]));
        }
        __syncthreads();
    }

    const int r0 = lane >> 2, c0 = (lane & 3) * 2;
#pragma unroll
    for (int mt = 0; mt < 4; mt++)
#pragma unroll
        for (int nt = 0; nt < 4; nt++) {
            int row = m0 + wm + mt * 16 + r0;
            int col = n0 + wn + nt * 8 + c0;
            float* p0 = C + (size_t)row * ldc + col;
            float* p1 = C + (size_t)(row + 8) * ldc + col;
            if (acc) {
                p0[0] += c[mt][nt][0]; p0[1] += c[mt][nt][1];
                p1[0] += c[mt][nt][2]; p1[1] += c[mt][nt][3];
            } else {
                p0[0] = c[mt][nt][0]; p0[1] = c[mt][nt][1];
                p1[0] = c[mt][nt][2]; p1[1] = c[mt][nt][3];
            }
        }
}

// ---------------- SGEMM (fp32 SIMT) for feature transforms X@W ----------------
__global__ void __launch_bounds__(256) sgemm(int M, int N, int K,
                                             const float* __restrict__ A,
                                             const float* __restrict__ B,
                                             float* __restrict__ C) {
    __shared__ float As[8][128];
    __shared__ float Bs[8][128];
    const int tid  = threadIdx.x;
    const int tx   = tid & 15;
    const int ty   = tid >> 4;
    const int row0 = blockIdx.y * 128;
    const int col0 = blockIdx.x * 128;
    const int a_row = tid >> 1, a_col = (tid & 1) << 2;
    const int b_row = tid >> 5, b_col = (tid & 31) << 2;

    float acc[8][8];
#pragma unroll
    for (int i = 0; i < 8; i++)
#pragma unroll
        for (int j = 0; j < 8; j++) acc[i][j] = 0.f;

    for (int kk = 0; kk < K; kk += 8) {
        float4 av = make_float4(0.f, 0.f, 0.f, 0.f);
        {
            int gm = row0 + a_row, gk = kk + a_col;
            if (gm < M && gk < K)
                av = *reinterpret_cast<const float4*>(A + (size_t)gm * K + gk);
        }
        As[a_col + 0][a_row] = av.x;
        As[a_col + 1][a_row] = av.y;
        As[a_col + 2][a_row] = av.z;
        As[a_col + 3][a_row] = av.w;

        float4 bv = make_float4(0.f, 0.f, 0.f, 0.f);
        {
            int gk = kk + b_row, gn = col0 + b_col;
            if (gk < K && gn < N)
                bv = *reinterpret_cast<const float4*>(B + (size_t)gk * N + gn);
        }
        *reinterpret_cast<float4*>(&Bs[b_row][b_col]) = bv;
        __syncthreads();

#pragma unroll
        for (int k = 0; k < 8; k++) {
            float4 a0 = *reinterpret_cast<const float4*>(&As[k][ty * 8]);
            float4 a1 = *reinterpret_cast<const float4*>(&As[k][ty * 8 + 4]);
            float4 b0 = *reinterpret_cast<const float4*>(&Bs[k][tx * 8]);
            float4 b1 = *reinterpret_cast<const float4*>(&Bs[k][tx * 8 + 4]);
            float a[8] = {a0.x, a0.y, a0.z, a0.w, a1.x, a1.y, a1.z, a1.w};
            float b[8] = {b0.x, b0.y, b0.z, b0.w, b1.x, b1.y, b1.z, b1.w};
#pragma unroll
            for (int i = 0; i < 8; i++)
#pragma unroll
                for (int j = 0; j < 8; j++) acc[i][j] += a[i] * b[j];
        }
        __syncthreads();
    }

#pragma unroll
    for (int i = 0; i < 8; i++) {
        int gm = row0 + ty * 8 + i;
        if (gm >= M) continue;
        float* Cr = C + (size_t)gm * N;
#pragma unroll
        for (int j = 0; j < 8; j++) {
            int gn = col0 + tx * 8 + j;
            if (gn < N) Cr[gn] = acc[i][j];
        }
    }
}

// ---------------- elementwise / graph kernels ----------------
__global__ void k_edges(const int* __restrict__ ei, int E, float* __restrict__ A) {
    int e = blockIdx.x * blockDim.x + threadIdx.x;
    if (e >= E) return;
    int s = ei[e], d = ei[E + e];
    A[(size_t)s * N0 + d] = 1.f;
    A[(size_t)d * N0 + s] = 1.f;
}

__global__ void k_dis(const float* __restrict__ A, int n, float* __restrict__ dis) {
    __shared__ float red[256];
    int row = blockIdx.x;
    const float* Ar = A + (size_t)row * n;
    float s = 0.f;
    for (int j = threadIdx.x; j < n; j += 256) s += Ar[j];
    red[threadIdx.x] = s;
    __syncthreads();
    for (int o = 128; o > 0; o >>= 1) {
        if (threadIdx.x < o) red[threadIdx.x] += red[threadIdx.x + o];
        __syncthreads();
    }
    if (threadIdx.x == 0) dis[row] = rsqrtf(red[0] + 1.0f);
}

// z = dis*xw split to bf16 hi/lo, padded to np rows x Cpad cols
__global__ void k_scale_pair(const float* __restrict__ xw, const float* __restrict__ dis,
                             int n, int np, int C, int Cpad,
                             __nv_bfloat16* __restrict__ zh, __nv_bfloat16* __restrict__ zl) {
    int i = blockIdx.x * blockDim.x + threadIdx.x;
    if (i >= np * Cpad) return;
    int r = i / Cpad, cc = i - r * Cpad;
    float v = (r < n && cc < C) ? dis[r] * xw[(size_t)r * C + cc] : 0.f;
    __nv_bfloat16 hi = __float2bfloat16(v);
    __nv_bfloat16 lo = __float2bfloat16(v - __bfloat162float(hi));
    zh[i] = hi;
    zl[i] = lo;
}

// z split stacked: zs1=[hi;lo], zs2=[lo;hi]  (2np x C)
__global__ void k_scale_pair_stk(const float* __restrict__ xw, const float* __restrict__ dis,
                                 int n, int np, int C,
                                 __nv_bfloat16* __restrict__ zs1, __nv_bfloat16* __restrict__ zs2) {
    int i = blockIdx.x * blockDim.x + threadIdx.x;
    if (i >= np * C) return;
    int r = i / C, cc = i - r * C;
    float v = (r < n) ? dis[r] * xw[(size_t)r * C + cc] : 0.f;
    __nv_bfloat16 hi = __float2bfloat16(v);
    __nv_bfloat16 lo = __float2bfloat16(v - __bfloat162float(hi));
    zs1[i] = hi;  zs1[(size_t)(np + r) * C + cc] = lo;
    zs2[i] = lo;  zs2[(size_t)(np + r) * C + cc] = hi;
}

// out = act(dis*t + b); t has leading dim ldt (t = (A+I)@z already includes +z)
__global__ void k_epilogue2(const float* __restrict__ t, int ldt,
                            const float* __restrict__ dis, const float* __restrict__ b,
                            int n, int C, float* __restrict__ out, int act) {
    int i = blockIdx.x * blockDim.x + threadIdx.x;
    if (i >= n * C) return;
    int r = i / C, cc = i - r * C;
    float v = dis[r] * t[(size_t)r * ldt + cc] + b[cc];
    if (act == ACT_RELU) v = fmaxf(v, 0.f);
    else if (act == ACT_SIGM) v = 1.f / (1.f + expf(-v));
    out[i] = v;
}

// bf16(A+I), zero-padded to np x np
__global__ void k_tobf16_adj(const float* __restrict__ A, int n, int np,
                             __nv_bfloat16* __restrict__ out) {
    int i = blockIdx.x * blockDim.x + threadIdx.x;
    if (i >= np * np) return;
    int r = i / np, cc = i - r * np;
    float v = 0.f;
    if (r < n && cc < n) v = A[(size_t)r * n + cc] + (r == cc ? 1.f : 0.f);
    out[i] = __float2bfloat16(v);
}

// exact split pack of (A+I): X=[hi|lo] (np x 2np)
__global__ void k_pack_X(const float* __restrict__ A, int n, int np,
                         __nv_bfloat16* __restrict__ X) {
    int i = blockIdx.x * blockDim.x + threadIdx.x;
    if (i >= np * np) return;
    int r = i / np, cc = i - r * np;
    float v = 0.f;
    if (r < n && cc < n) v = A[(size_t)r * n + cc] + (r == cc ? 1.f : 0.f);
    __nv_bfloat16 hi = __float2bfloat16(v);
    __nv_bfloat16 lo = __float2bfloat16(v - __bfloat162float(hi));
    X[(size_t)r * (2 * np) + cc]      = hi;
    X[(size_t)r * (2 * np) + np + cc] = lo;
}

// stacked Y operands for split augment: Y1=[hi;lo], Y2=[lo;hi]  (2np x np)
__global__ void k_pack_Y(const float* __restrict__ A, int n, int np,
                         __nv_bfloat16* __restrict__ Y1, __nv_bfloat16* __restrict__ Y2) {
    int i = blockIdx.x * blockDim.x + threadIdx.x;
    if (i >= np * np) return;
    int r = i / np, cc = i - r * np;
    float v = 0.f;
    if (r < n && cc < n) v = A[(size_t)r * n + cc] + (r == cc ? 1.f : 0.f);
    __nv_bfloat16 hi = __float2bfloat16(v);
    __nv_bfloat16 lo = __float2bfloat16(v - __bfloat162float(hi));
    Y1[(size_t)r * np + cc]        = hi;
    Y1[(size_t)(np + r) * np + cc] = lo;
    Y2[(size_t)r * np + cc]        = lo;
    Y2[(size_t)(np + r) * np + cc] = hi;
}

__global__ void k_zero_diag_ld(float* __restrict__ A, int n, int ld) {
    int i = blockIdx.x * blockDim.x + threadIdx.x;
    if (i < n) A[(size_t)i * ld + i] = 0.0f;
}

__global__ void k_pnorm(const float* __restrict__ p, int n, float* __restrict__ out) {
    __shared__ float red[256];
    float s = 0.f;
    for (int i = threadIdx.x; i < n; i += 256) s += p[i] * p[i];
    red[threadIdx.x] = s;
    __syncthreads();
    for (int o = 128; o > 0; o >>= 1) {
        if (threadIdx.x < o) red[threadIdx.x] += red[threadIdx.x + o];
        __syncthreads();
    }
    if (threadIdx.x == 0) out[0] = sqrtf(red[0]);
}

__global__ void k_scores(const float* __restrict__ h, int n, int C,
                         const float* __restrict__ p, const float* __restrict__ pn,
                         float* __restrict__ score) {
    int row = blockIdx.x * 8 + (threadIdx.x >> 5);
    int lane = threadIdx.x & 31;
    if (row >= n) return;
    const float* hr = h + (size_t)row * C;
    float s = 0.f;
    for (int cc = lane; cc < C; cc += 32) s += hr[cc] * p[cc];
    for (int o = 16; o > 0; o >>= 1) s += __shfl_xor_sync(0xffffffffu, s, o);
    if (lane == 0) score[row] = tanhf(s / pn[0]);
}

__global__ void __launch_bounds__(1024) k_sort_topk(const float* __restrict__ score,
                                                    int n, int npad, int k,
                                                    int* __restrict__ perm) {
    __shared__ float skey[4096];
    __shared__ int   sidx[4096];
    for (int i = threadIdx.x; i < npad; i += blockDim.x) {
        skey[i] = (i < n) ? score[i] : -INFINITY;
        sidx[i] = i;
    }
    __syncthreads();
    for (int kk = 2; kk <= npad; kk <<= 1) {
        for (int j = kk >> 1; j > 0; j >>= 1) {
            for (int i = threadIdx.x; i < npad; i += blockDim.x) {
                int ixj = i ^ j;
                if (ixj > i) {
                    float a = skey[i], b = skey[ixj];
                    bool sw = ((i & kk) == 0) ? (a < b) : (a > b);
                    if (sw) {
                        skey[i] = b; skey[ixj] = a;
                        int t = sidx[i]; sidx[i] = sidx[ixj]; sidx[ixj] = t;
                    }
                }
            }
            __syncthreads();
        }
    }
    for (int i = threadIdx.x; i < k; i += blockDim.x) perm[i] = sidx[i];
}

__global__ void k_gatherX(const float* __restrict__ h, int C,
                          const int* __restrict__ perm, const float* __restrict__ score,
                          int k, float* __restrict__ out) {
    int i = blockIdx.x * blockDim.x + threadIdx.x;
    if (i >= k * C) return;
    int r = i / C, cc = i - r * C;
    int pr = perm[r];
    out[i] = h[(size_t)pr * C + cc] * score[pr];
}

__global__ void k_gatherA(const float* __restrict__ Asrc, int srcld,
                          const int* __restrict__ perm, int k, float* __restrict__ Adst) {
    int cc = blockIdx.x * blockDim.x + threadIdx.x;
    int r = blockIdx.y;
    if (cc < k) Adst[(size_t)r * k + cc] = Asrc[(size_t)perm[r] * srcld + perm[cc]];
}

__global__ void k_scatter_add(float* __restrict__ u, const float* __restrict__ h,
                              const int* __restrict__ perm, int k, int C) {
    int i = blockIdx.x * blockDim.x + threadIdx.x;
    if (i >= k * C) return;
    int r = i / C, cc = i - r * C;
    u[(size_t)perm[r] * C + cc] += h[i];
}

// ---------------- host orchestration ----------------
static void run_sgemm(int M, int N, int K, const float* A, const float* B, float* C) {
    dim3 g((N + 127) / 128, (M + 127) / 128);
    sgemm<<<g, 256>>>(M, N, K, A, B, C);
}

static void run_hgemm(int M, int N, int K, const __nv_bfloat16* A, int lda,
                      const __nv_bfloat16* B, int ldb, float* C, int ldc, int acc) {
    dim3 g(N / 128, M / 128);
    hgemm<<<g, 256>>>(M, N, K, A, lda, B, ldb, C, ldc, acc);
}

// GCN, exact-bf16 adjacency path: out = act(dis .* ((A+I)@(dis.*xw)) + b)
static void run_gcn_exact(const float* Afp, const __nv_bfloat16* bApI, int n, int np,
                          const float* X, int inC, const float* W, int outC, const float* b,
                          float* out, int act,
                          float* xw, float* t, float* dis,
                          __nv_bfloat16* zh, __nv_bfloat16* zl) {
    run_sgemm(n, outC, inC, X, W, xw);
    k_dis<<<n, 256>>>(Afp, n, dis);
    int Cpad = (outC % 128 == 0) ? outC : 128;
    int tot = np * Cpad;
    k_scale_pair<<<(tot + 255) / 256, 256>>>(xw, dis, n, np, outC, Cpad, zh, zl);
    run_hgemm(np, Cpad, np, bApI, np, zh, Cpad, t, Cpad, 0);
    run_hgemm(np, Cpad, np, bApI, np, zl, Cpad, t, Cpad, 1);
    int nc = n * outC;
    k_epilogue2<<<(nc + 255) / 256, 256>>>(t, Cpad, dis, b, n, outC, out, act);
}

// GCN, split-adjacency path (adjacency entries may exceed bf16-exact range)
static void run_gcn_split(const float* Afp, const __nv_bfloat16* X2, int n, int np,
                          const float* X, int inC, const float* W, int outC, const float* b,
                          float* out, int act,
                          float* xw, float* t, float* dis,
                          __nv_bfloat16* zs1, __nv_bfloat16* zs2) {
    run_sgemm(n, outC, inC, X, W, xw);
    k_dis<<<n, 256>>>(Afp, n, dis);
    int tot = np * outC;
    k_scale_pair_stk<<<(tot + 255) / 256, 256>>>(xw, dis, n, np, outC, zs1, zs2);
    run_hgemm(np, outC, 2 * np, X2, 2 * np, zs1, outC, t, outC, 0);
    run_hgemm(np, outC, 2 * np, X2, 2 * np, zs2, outC, t, outC, 1);
    int nc = n * outC;
    k_epilogue2<<<(nc + 255) / 256, 256>>>(t, outC, dis, b, n, outC, out, act);
}

static void run_pool(const float* h, int n, int npad, const float* p, int k,
                     const float* Aug, int augld, int* perm, float* xk, float* Ak,
                     float* score, float* pn) {
    k_pnorm<<<1, 256>>>(p, HC, pn);
    k_scores<<<(n + 7) / 8, 256>>>(h, n, HC, p, pn, score);
    k_sort_topk<<<1, 1024>>>(score, n, npad, k, perm);
    k_gatherX<<<(k * HC + 255) / 256, 256>>>(h, HC, perm, score, k, xk);
    dim3 ga((k + 255) / 256, k);
    k_gatherA<<<ga, 256>>>(Aug, augld, perm, k, Ak);
}

extern "C" void kernel_launch(void* const* d_in, const int* in_sizes, int n_in,
                              void* d_out, int out_size) {
    const float* x   = (const float*)d_in[0];
    const int*   ei  = (const int*)  d_in[1];
    const float* Wd0 = (const float*)d_in[2];  const float* bd0 = (const float*)d_in[3];
    const float* Wd1 = (const float*)d_in[4];  const float* bd1 = (const float*)d_in[5];
    const float* Wd2 = (const float*)d_in[6];  const float* bd2 = (const float*)d_in[7];
    const float* Wd3 = (const float*)d_in[8];  const float* bd3 = (const float*)d_in[9];
    const float* p1  = (const float*)d_in[10];
    const float* p2  = (const float*)d_in[11];
    const float* p3  = (const float*)d_in[12];
    const float* Wu0 = (const float*)d_in[13]; const float* bu0 = (const float*)d_in[14];
    const float* Wu1 = (const float*)d_in[15]; const float* bu1 = (const float*)d_in[16];
    const float* Wu2 = (const float*)d_in[17]; const float* bu2 = (const float*)d_in[18];
    const int E = in_sizes[1] / 2;

    float *A0, *Aug, *A1, *A2, *A3, *h0, *h1, *h2, *h3, *hb;
    float *xw, *t, *u, *dis, *sc, *pn;
    int *pm0, *pm1, *pm2;
    __nv_bfloat16 *bA0, *bA1, *bX2, *bX3, *bY1, *bY2, *bzh, *bzl, *bzs1, *bzs2;
    cudaGetSymbolAddress((void**)&A0,  g_A0);
    cudaGetSymbolAddress((void**)&Aug, g_Aug);
    cudaGetSymbolAddress((void**)&A1,  g_A1);
    cudaGetSymbolAddress((void**)&A2,  g_A2);
    cudaGetSymbolAddress((void**)&A3,  g_A3);
    cudaGetSymbolAddress((void**)&h0,  g_h0);
    cudaGetSymbolAddress((void**)&h1,  g_h1);
    cudaGetSymbolAddress((void**)&h2,  g_h2);
    cudaGetSymbolAddress((void**)&h3,  g_h3);
    cudaGetSymbolAddress((void**)&hb,  g_hb);
    cudaGetSymbolAddress((void**)&xw,  g_xw);
    cudaGetSymbolAddress((void**)&t,   g_t);
    cudaGetSymbolAddress((void**)&u,   g_u);
    cudaGetSymbolAddress((void**)&dis, g_dis);
    cudaGetSymbolAddress((void**)&sc,  g_sc);
    cudaGetSymbolAddress((void**)&pn,  g_pn);
    cudaGetSymbolAddress((void**)&pm0, g_perm0);
    cudaGetSymbolAddress((void**)&pm1, g_perm1);
    cudaGetSymbolAddress((void**)&pm2, g_perm2);
    cudaGetSymbolAddress((void**)&bA0, g_bA0);
    cudaGetSymbolAddress((void**)&bA1, g_bA1);
    cudaGetSymbolAddress((void**)&bX2, g_bX2);
    cudaGetSymbolAddress((void**)&bX3, g_bX3);
    cudaGetSymbolAddress((void**)&bY1, g_bY1);
    cudaGetSymbolAddress((void**)&bY2, g_bY2);
    cudaGetSymbolAddress((void**)&bzh, g_bzh);
    cudaGetSymbolAddress((void**)&bzl, g_bzl);
    cudaGetSymbolAddress((void**)&bzs1, g_bzs1);
    cudaGetSymbolAddress((void**)&bzs2, g_bzs2);

    // ---- build dense adjacency ----
    cudaMemsetAsync(A0, 0, (size_t)N0 * N0 * sizeof(float), 0);
    k_edges<<<(E + 255) / 256, 256>>>(ei, E, A0);
    k_tobf16_adj<<<(N0 * N0 + 255) / 256, 256>>>(A0, N0, N0, bA0);   // bf16(A0+I), exact

    // ---- down path ----
    run_gcn_exact(A0, bA0, N0, 4096, x, INC, Wd0, HC, bd0, h0, ACT_RELU,
                  xw, t, dis, bzh, bzl);

    // augment0 = (A0+I)^2, diag zeroed (exact in bf16)
    run_hgemm(4096, 4096, 4096, bA0, 4096, bA0, 4096, Aug, 4096, 0);
    k_zero_diag_ld<<<(N0 + 255) / 256, 256>>>(Aug, N0, 4096);
    run_pool(h0, N0, 4096, p1, KP1, Aug, 4096, pm0, u, A1, sc, pn);
    k_tobf16_adj<<<(2048 * 2048 + 255) / 256, 256>>>(A1, KP1, 2048, bA1);  // bf16(A1+I), exact (small ints)
    run_gcn_exact(A1, bA1, KP1, 2048, u, HC, Wd1, HC, bd1, h1, ACT_RELU,
                  xw, t, dis, bzh, bzl);

    // augment1 = (A1+I)^2 (small-int entries, exact in bf16)
    run_hgemm(2048, 2048, 2048, bA1, 2048, bA1, 2048, Aug, 2048, 0);
    k_zero_diag_ld<<<(KP1 + 255) / 256, 256>>>(Aug, KP1, 2048);
    run_pool(h1, KP1, 2048, p2, KP2, Aug, 2048, pm1, u, A2, sc, pn);
    k_pack_X<<<(1024 * 1024 + 255) / 256, 256>>>(A2, KP2, 1024, bX2);     // (A2+I) hi/lo split
    run_gcn_split(A2, bX2, KP2, 1024, u, HC, Wd2, HC, bd2, h2, ACT_RELU,
                  xw, t, dis, bzs1, bzs2);

    // augment2 = (A2+I)^2 via exact hi/lo split
    k_pack_Y<<<(1024 * 1024 + 255) / 256, 256>>>(A2, KP2, 1024, bY1, bY2);
    run_hgemm(1024, 1024, 2048, bX2, 2048, bY1, 1024, Aug, 1024, 0);
    run_hgemm(1024, 1024, 2048, bX2, 2048, bY2, 1024, Aug, 1024, 1);
    k_zero_diag_ld<<<(KP2 + 255) / 256, 256>>>(Aug, KP2, 1024);
    run_pool(h2, KP2, 1024, p3, KP3, Aug, 1024, pm2, u, A3, sc, pn);
    k_pack_X<<<(512 * 512 + 255) / 256, 256>>>(A3, KP3, 512, bX3);        // (A3+I) hi/lo split
    run_gcn_split(A3, bX3, KP3, 512, u, HC, Wd3, HC, bd3, h3, ACT_RELU,
                  xw, t, dis, bzs1, bzs2);

    // ---- up path ----
    cudaMemcpyAsync(u, h2, (size_t)KP2 * HC * sizeof(float), cudaMemcpyDeviceToDevice, 0);
    k_scatter_add<<<(KP3 * HC + 255) / 256, 256>>>(u, h3, pm2, KP3, HC);
    run_gcn_split(A2, bX2, KP2, 1024, u, HC, Wu0, HC, bu0, hb, ACT_RELU,
                  xw, t, dis, bzs1, bzs2);

    cudaMemcpyAsync(u, h1, (size_t)KP1 * HC * sizeof(float), cudaMemcpyDeviceToDevice, 0);
    k_scatter_add<<<(KP2 * HC + 255) / 256, 256>>>(u, hb, pm1, KP2, HC);
    run_gcn_exact(A1, bA1, KP1, 2048, u, HC, Wu1, HC, bu1, hb, ACT_RELU,
                  xw, t, dis, bzh, bzl);

    cudaMemcpyAsync(u, h0, (size_t)N0 * HC * sizeof(float), cudaMemcpyDeviceToDevice, 0);
    k_scatter_add<<<(KP1 * HC + 255) / 256, 256>>>(u, hb, pm0, KP1, HC);
    run_gcn_exact(A0, bA0, N0, 4096, u, HC, Wu2, OC, bu2, (float*)d_out, ACT_SIGM,
                  xw, t, dis, bzh, bzl);
}

// round 5
// speedup vs baseline: 3.4752x; 1.1578x over previous
#include <cuda_runtime.h>
#include <cuda_bf16.h>
#include <cstdint>
#include <math.h>

// ---------------- problem constants ----------------
#define N0   4096
#define INC  128
#define HC   512
#define OC   64
#define KP1  2000
#define KP2  1000
#define KP3  500

#define ACT_NONE 0
#define ACT_RELU 1
#define ACT_SIGM 2

// ---------------- scratch (device globals; allocation-free) ----------------
__device__ float g_A0 [(size_t)N0*N0];      // fp32 level-0 adjacency
__device__ float g_Augp[(size_t)2048*2048]; // pooled augment product (ld=kpad)
__device__ float g_A1 [(size_t)KP1*KP1];
__device__ float g_A2 [(size_t)KP2*KP2];
__device__ float g_A3 [(size_t)KP3*KP3];
__device__ float g_h0 [(size_t)N0*HC];
__device__ float g_h1 [(size_t)KP1*HC];
__device__ float g_h2 [(size_t)KP2*HC];
__device__ float g_h3 [(size_t)KP3*HC];
__device__ float g_hb [(size_t)KP1*HC];
__device__ float g_xw [(size_t)N0*HC];
__device__ float g_t  [(size_t)N0*HC];
__device__ float g_u  [(size_t)N0*HC];
__device__ float g_dis[N0];
__device__ float g_sc [N0];
__device__ float g_pn [1];
__device__ int   g_perm0[KP1];
__device__ int   g_perm1[KP2];
__device__ int   g_perm2[KP3];
// bf16 tensor-core operands
__device__ __nv_bfloat16 g_bA0 [(size_t)4096*4096];  // bf16(A0+I) padded
__device__ __nv_bfloat16 g_bA1 [(size_t)2048*2048];  // bf16(A1+I) padded
__device__ __nv_bfloat16 g_bX2 [(size_t)1024*2048];  // (A2+I) split [hi|lo]
__device__ __nv_bfloat16 g_bX3 [(size_t)512*1024];   // (A3+I) split [hi|lo]
__device__ __nv_bfloat16 g_G  [(size_t)2048*4096];   // gathered rows (kpad x np)
__device__ __nv_bfloat16 g_Gt [(size_t)4096*2048];   // gathered cols (np x kpad) / Y1
__device__ __nv_bfloat16 g_Y2 [(size_t)2048*1024];   // split-augment second operand
__device__ __nv_bfloat16 g_bzh [(size_t)4096*512];   // z hi
__device__ __nv_bfloat16 g_bzl [(size_t)4096*512];   // z lo
__device__ __nv_bfloat16 g_bzs1[(size_t)2048*512];   // [zh;zl]
__device__ __nv_bfloat16 g_bzs2[(size_t)2048*512];   // [zl;zh]

// ---------------- cp.async helpers ----------------
#define CPASYNC16(dst_u32, src_ptr) \
    asm volatile("cp.async.ca.shared.global [%0], [%1], 16;" :: "r"(dst_u32), "l"(src_ptr))
#define CP_COMMIT() asm volatile("cp.async.commit_group;")

// ---------------- bf16 tensor-core GEMM (2-stage cp.async pipeline) ----------------
// C(MxN fp32) = A(MxK bf16,row,lda) @ B(KxN bf16,row,ldb); M,N mult of 128, K mult of 32.
__global__ void __launch_bounds__(256) hgemm(int M, int N, int K,
        const __nv_bfloat16* __restrict__ A, int lda,
        const __nv_bfloat16* __restrict__ B, int ldb,
        float* __restrict__ C, int ldc, int acc) {
    __shared__ __nv_bfloat16 As[2][128][40];
    __shared__ __nv_bfloat16 Bs[2][32][136];
    const int tid  = threadIdx.x;
    const int lane = tid & 31;
    const int warp = tid >> 5;
    const int wm = (warp >> 2) * 64;
    const int wn = (warp & 3) * 32;
    const int m0 = blockIdx.y * 128;
    const int n0 = blockIdx.x * 128;

    const int ar = tid >> 1, ac = (tid & 1) * 16;
    const int br = tid >> 3, bc = (tid & 7) * 16;

    float c[4][4][4];
#pragma unroll
    for (int mt = 0; mt < 4; mt++)
#pragma unroll
        for (int nt = 0; nt < 4; nt++)
#pragma unroll
            for (int r = 0; r < 4; r++) c[mt][nt][r] = 0.f;

    const int ntile = K >> 5;

    {
        unsigned da = (unsigned)__cvta_generic_to_shared(&As[0][ar][ac]);
        const __nv_bfloat16* pa = A + (size_t)(m0 + ar) * lda + ac;
        CPASYNC16(da, pa);
        CPASYNC16(da + 16, pa + 8);
        unsigned db = (unsigned)__cvta_generic_to_shared(&Bs[0][br][bc]);
        const __nv_bfloat16* pb = B + (size_t)br * ldb + n0 + bc;
        CPASYNC16(db, pb);
        CPASYNC16(db + 16, pb + 8);
        CP_COMMIT();
    }

    for (int it = 0; it < ntile; ++it) {
        if (it + 1 < ntile) {
            int s = (it + 1) & 1, kk = (it + 1) << 5;
            unsigned da = (unsigned)__cvta_generic_to_shared(&As[s][ar][ac]);
            const __nv_bfloat16* pa = A + (size_t)(m0 + ar) * lda + kk + ac;
            CPASYNC16(da, pa);
            CPASYNC16(da + 16, pa + 8);
            unsigned db = (unsigned)__cvta_generic_to_shared(&Bs[s][br][bc]);
            const __nv_bfloat16* pb = B + (size_t)(kk + br) * ldb + n0 + bc;
            CPASYNC16(db, pb);
            CPASYNC16(db + 16, pb + 8);
            CP_COMMIT();
            asm volatile("cp.async.wait_group 1;");
        } else {
            asm volatile("cp.async.wait_group 0;");
        }
        __syncthreads();

        const int s = it & 1;
#pragma unroll
        for (int ks = 0; ks < 32; ks += 16) {
            uint32_t af[4][4];
#pragma unroll
            for (int mt = 0; mt < 4; mt++) {
                unsigned addr = (unsigned)__cvta_generic_to_shared(
                    &As[s][wm + mt * 16 + (lane & 15)][ks + (lane >> 4) * 8]);
                asm volatile("ldmatrix.sync.aligned.m8n8.x4.shared.b16 {%0,%1,%2,%3}, [%4];"
                    : "=r"(af[mt][0]), "=r"(af[mt][1]), "=r"(af[mt][2]), "=r"(af[mt][3])
                    : "r"(addr));
            }
            uint32_t bfr[4][2];
#pragma unroll
            for (int nt = 0; nt < 4; nt++) {
                unsigned addr = (unsigned)__cvta_generic_to_shared(
                    &Bs[s][ks + (lane & 15)][wn + nt * 8]);
                asm volatile("ldmatrix.sync.aligned.m8n8.x2.trans.shared.b16 {%0,%1}, [%2];"
                    : "=r"(bfr[nt][0]), "=r"(bfr[nt][1]) : "r"(addr));
            }
#pragma unroll
            for (int mt = 0; mt < 4; mt++)
#pragma unroll
                for (int nt = 0; nt < 4; nt++)
                    asm volatile(
                        "mma.sync.aligned.m16n8k16.row.col.f32.bf16.bf16.f32 "
                        "{%0,%1,%2,%3}, {%4,%5,%6,%7}, {%8,%9}, {%0,%1,%2,%3};"
                        : "+f"(c[mt][nt][0]), "+f"(c[mt][nt][1]),
                          "+f"(c[mt][nt][2]), "+f"(c[mt][nt][3])
                        : "r"(af[mt][0]), "r"(af[mt][1]), "r"(af[mt][2]), "r"(af[mt][3]),
                          "r"(bfr[nt][0]), "r"(bfr[nt][1]));
        }
        __syncthreads();
    }

    const int r0 = lane >> 2, c0 = (lane & 3) * 2;
#pragma unroll
    for (int mt = 0; mt < 4; mt++)
#pragma unroll
        for (int nt = 0; nt < 4; nt++) {
            int row = m0 + wm + mt * 16 + r0;
            int col = n0 + wn + nt * 8 + c0;
            float* p0 = C + (size_t)row * ldc + col;
            float* p1 = C + (size_t)(row + 8) * ldc + col;
            if (acc) {
                p0[0] += c[mt][nt][0]; p0[1] += c[mt][nt][1];
                p1[0] += c[mt][nt][2]; p1[1] += c[mt][nt][3];
            } else {
                p0[0] = c[mt][nt][0]; p0[1] = c[mt][nt][1];
                p1[0] = c[mt][nt][2]; p1[1] = c[mt][nt][3];
            }
        }
}

// ---------------- SGEMM (fp32 SIMT) for feature transforms X@W ----------------
__global__ void __launch_bounds__(256) sgemm(int M, int N, int K,
                                             const float* __restrict__ A,
                                             const float* __restrict__ B,
                                             float* __restrict__ C) {
    __shared__ float As[8][128];
    __shared__ float Bs[8][128];
    const int tid  = threadIdx.x;
    const int tx   = tid & 15;
    const int ty   = tid >> 4;
    const int row0 = blockIdx.y * 128;
    const int col0 = blockIdx.x * 128;
    const int a_row = tid >> 1, a_col = (tid & 1) << 2;
    const int b_row = tid >> 5, b_col = (tid & 31) << 2;

    float acc[8][8];
#pragma unroll
    for (int i = 0; i < 8; i++)
#pragma unroll
        for (int j = 0; j < 8; j++) acc[i][j] = 0.f;

    for (int kk = 0; kk < K; kk += 8) {
        float4 av = make_float4(0.f, 0.f, 0.f, 0.f);
        {
            int gm = row0 + a_row, gk = kk + a_col;
            if (gm < M && gk < K)
                av = *reinterpret_cast<const float4*>(A + (size_t)gm * K + gk);
        }
        As[a_col + 0][a_row] = av.x;
        As[a_col + 1][a_row] = av.y;
        As[a_col + 2][a_row] = av.z;
        As[a_col + 3][a_row] = av.w;

        float4 bv = make_float4(0.f, 0.f, 0.f, 0.f);
        {
            int gk = kk + b_row, gn = col0 + b_col;
            if (gk < K && gn < N)
                bv = *reinterpret_cast<const float4*>(B + (size_t)gk * N + gn);
        }
        *reinterpret_cast<float4*>(&Bs[b_row][b_col]) = bv;
        __syncthreads();

#pragma unroll
        for (int k = 0; k < 8; k++) {
            float4 a0 = *reinterpret_cast<const float4*>(&As[k][ty * 8]);
            float4 a1 = *reinterpret_cast<const float4*>(&As[k][ty * 8 + 4]);
            float4 b0 = *reinterpret_cast<const float4*>(&Bs[k][tx * 8]);
            float4 b1 = *reinterpret_cast<const float4*>(&Bs[k][tx * 8 + 4]);
            float a[8] = {a0.x, a0.y, a0.z, a0.w, a1.x, a1.y, a1.z, a1.w};
            float b[8] = {b0.x, b0.y, b0.z, b0.w, b1.x, b1.y, b1.z, b1.w};
#pragma unroll
            for (int i = 0; i < 8; i++)
#pragma unroll
                for (int j = 0; j < 8; j++) acc[i][j] += a[i] * b[j];
        }
        __syncthreads();
    }

#pragma unroll
    for (int i = 0; i < 8; i++) {
        int gm = row0 + ty * 8 + i;
        if (gm >= M) continue;
        float* Cr = C + (size_t)gm * N;
#pragma unroll
        for (int j = 0; j < 8; j++) {
            int gn = col0 + tx * 8 + j;
            if (gn < N) Cr[gn] = acc[i][j];
        }
    }
}

// ---------------- elementwise / graph kernels ----------------
__global__ void k_edges(const int* __restrict__ ei, int E, float* __restrict__ A) {
    int e = blockIdx.x * blockDim.x + threadIdx.x;
    if (e >= E) return;
    int s = ei[e], d = ei[E + e];
    A[(size_t)s * N0 + d] = 1.f;
    A[(size_t)d * N0 + s] = 1.f;
}

__global__ void k_dis(const float* __restrict__ A, int n, float* __restrict__ dis) {
    __shared__ float red[256];
    int row = blockIdx.x;
    const float* Ar = A + (size_t)row * n;
    float s = 0.f;
    for (int j = threadIdx.x; j < n; j += 256) s += Ar[j];
    red[threadIdx.x] = s;
    __syncthreads();
    for (int o = 128; o > 0; o >>= 1) {
        if (threadIdx.x < o) red[threadIdx.x] += red[threadIdx.x + o];
        __syncthreads();
    }
    if (threadIdx.x == 0) dis[row] = rsqrtf(red[0] + 1.0f);
}

// z = dis*xw split to bf16 hi/lo, padded to np rows x Cpad cols
__global__ void k_scale_pair(const float* __restrict__ xw, const float* __restrict__ dis,
                             int n, int np, int C, int Cpad,
                             __nv_bfloat16* __restrict__ zh, __nv_bfloat16* __restrict__ zl) {
    int i = blockIdx.x * blockDim.x + threadIdx.x;
    if (i >= np * Cpad) return;
    int r = i / Cpad, cc = i - r * Cpad;
    float v = (r < n && cc < C) ? dis[r] * xw[(size_t)r * C + cc] : 0.f;
    __nv_bfloat16 hi = __float2bfloat16(v);
    __nv_bfloat16 lo = __float2bfloat16(v - __bfloat162float(hi));
    zh[i] = hi;
    zl[i] = lo;
}

// z split stacked: zs1=[hi;lo], zs2=[lo;hi]  (2np x C)
__global__ void k_scale_pair_stk(const float* __restrict__ xw, const float* __restrict__ dis,
                                 int n, int np, int C,
                                 __nv_bfloat16* __restrict__ zs1, __nv_bfloat16* __restrict__ zs2) {
    int i = blockIdx.x * blockDim.x + threadIdx.x;
    if (i >= np * C) return;
    int r = i / C, cc = i - r * C;
    float v = (r < n) ? dis[r] * xw[(size_t)r * C + cc] : 0.f;
    __nv_bfloat16 hi = __float2bfloat16(v);
    __nv_bfloat16 lo = __float2bfloat16(v - __bfloat162float(hi));
    zs1[i] = hi;  zs1[(size_t)(np + r) * C + cc] = lo;
    zs2[i] = lo;  zs2[(size_t)(np + r) * C + cc] = hi;
}

// out = act(dis*t + b); t has leading dim ldt
__global__ void k_epilogue2(const float* __restrict__ t, int ldt,
                            const float* __restrict__ dis, const float* __restrict__ b,
                            int n, int C, float* __restrict__ out, int act) {
    int i = blockIdx.x * blockDim.x + threadIdx.x;
    if (i >= n * C) return;
    int r = i / C, cc = i - r * C;
    float v = dis[r] * t[(size_t)r * ldt + cc] + b[cc];
    if (act == ACT_RELU) v = fmaxf(v, 0.f);
    else if (act == ACT_SIGM) v = 1.f / (1.f + expf(-v));
    out[i] = v;
}

// bf16(A+I), zero-padded to np x np
__global__ void k_tobf16_adj(const float* __restrict__ A, int n, int np,
                             __nv_bfloat16* __restrict__ out) {
    int i = blockIdx.x * blockDim.x + threadIdx.x;
    if (i >= np * np) return;
    int r = i / np, cc = i - r * np;
    float v = 0.f;
    if (r < n && cc < n) v = A[(size_t)r * n + cc] + (r == cc ? 1.f : 0.f);
    out[i] = __float2bfloat16(v);
}

// exact split pack of (A+I): X=[hi|lo] (np x 2np)
__global__ void k_pack_X(const float* __restrict__ A, int n, int np,
                         __nv_bfloat16* __restrict__ X) {
    int i = blockIdx.x * blockDim.x + threadIdx.x;
    if (i >= np * np) return;
    int r = i / np, cc = i - r * np;
    float v = 0.f;
    if (r < n && cc < n) v = A[(size_t)r * n + cc] + (r == cc ? 1.f : 0.f);
    __nv_bfloat16 hi = __float2bfloat16(v);
    __nv_bfloat16 lo = __float2bfloat16(v - __bfloat162float(hi));
    X[(size_t)r * (2 * np) + cc]      = hi;
    X[(size_t)r * (2 * np) + np + cc] = lo;
}

// G[r][:] = bApI[perm[r]][:]  (kpad x np, zero-pad rows >= k)
__global__ void k_gather_rows(const __nv_bfloat16* __restrict__ bApI, int np,
                              const int* __restrict__ perm, int k, int kpad,
                              __nv_bfloat16* __restrict__ G) {
    int i = blockIdx.x * blockDim.x + threadIdx.x;
    if (i >= kpad * np) return;
    int r = i / np, j = i - r * np;
    G[i] = (r < k) ? bApI[(size_t)perm[r] * np + j] : __float2bfloat16(0.f);
}

// Gt[j][r] = bApI[j][perm[r]]  (np x kpad)
__global__ void k_gather_cols(const __nv_bfloat16* __restrict__ bApI, int np,
                              const int* __restrict__ perm, int k, int kpad,
                              __nv_bfloat16* __restrict__ Gt) {
    int i = blockIdx.x * blockDim.x + threadIdx.x;
    if (i >= np * kpad) return;
    int j = i / kpad, r = i - j * kpad;
    Gt[i] = (r < k) ? bApI[(size_t)j * np + perm[r]] : __float2bfloat16(0.f);
}

// split-gather rows of (A+I) at perm: Xg[r][:] = [hi | lo]  (kpad x 2np)
__global__ void k_gather_rows_split(const float* __restrict__ A, int n, int np,
                                    const int* __restrict__ perm, int k, int kpad,
                                    __nv_bfloat16* __restrict__ Xg) {
    int i = blockIdx.x * blockDim.x + threadIdx.x;
    if (i >= kpad * np) return;
    int r = i / np, j = i - r * np;
    float v = 0.f;
    if (r < k && j < n) {
        int pr = perm[r];
        v = A[(size_t)pr * n + j] + (pr == j ? 1.f : 0.f);
    }
    __nv_bfloat16 hi = __float2bfloat16(v);
    __nv_bfloat16 lo = __float2bfloat16(v - __bfloat162float(hi));
    Xg[(size_t)r * (2 * np) + j]      = hi;
    Xg[(size_t)r * (2 * np) + np + j] = lo;
}

// split-gather cols: Y1=[hi;lo], Y2=[lo;hi]  (2np x kpad); Y*[j][c] from (A+I)[perm[c]][j]
__global__ void k_gather_cols_split(const float* __restrict__ A, int n, int np,
                                    const int* __restrict__ perm, int k, int kpad,
                                    __nv_bfloat16* __restrict__ Y1,
                                    __nv_bfloat16* __restrict__ Y2) {
    int i = blockIdx.x * blockDim.x + threadIdx.x;
    if (i >= np * kpad) return;
    int j = i / kpad, cc = i - j * kpad;
    float v = 0.f;
    if (cc < k && j < n) {
        int pc = perm[cc];
        v = A[(size_t)pc * n + j] + (pc == j ? 1.f : 0.f);
    }
    __nv_bfloat16 hi = __float2bfloat16(v);
    __nv_bfloat16 lo = __float2bfloat16(v - __bfloat162float(hi));
    Y1[(size_t)j * kpad + cc]        = hi;
    Y1[(size_t)(np + j) * kpad + cc] = lo;
    Y2[(size_t)j * kpad + cc]        = lo;
    Y2[(size_t)(np + j) * kpad + cc] = hi;
}

// Adst(k x k) = Augp(ld=kpad) cropped, diag zeroed
__global__ void k_crop_diag(const float* __restrict__ Augp, int kpad, int k,
                            float* __restrict__ Adst) {
    int i = blockIdx.x * blockDim.x + threadIdx.x;
    if (i >= k * k) return;
    int r = i / k, cc = i - r * k;
    Adst[i] = (r == cc) ? 0.f : Augp[(size_t)r * kpad + cc];
}

__global__ void k_pnorm(const float* __restrict__ p, int n, float* __restrict__ out) {
    __shared__ float red[256];
    float s = 0.f;
    for (int i = threadIdx.x; i < n; i += 256) s += p[i] * p[i];
    red[threadIdx.x] = s;
    __syncthreads();
    for (int o = 128; o > 0; o >>= 1) {
        if (threadIdx.x < o) red[threadIdx.x] += red[threadIdx.x + o];
        __syncthreads();
    }
    if (threadIdx.x == 0) out[0] = sqrtf(red[0]);
}

__global__ void k_scores(const float* __restrict__ h, int n, int C,
                         const float* __restrict__ p, const float* __restrict__ pn,
                         float* __restrict__ score) {
    int row = blockIdx.x * 8 + (threadIdx.x >> 5);
    int lane = threadIdx.x & 31;
    if (row >= n) return;
    const float* hr = h + (size_t)row * C;
    float s = 0.f;
    for (int cc = lane; cc < C; cc += 32) s += hr[cc] * p[cc];
    for (int o = 16; o > 0; o >>= 1) s += __shfl_xor_sync(0xffffffffu, s, o);
    if (lane == 0) score[row] = tanhf(s / pn[0]);
}

__global__ void __launch_bounds__(1024) k_sort_topk(const float* __restrict__ score,
                                                    int n, int npad, int k,
                                                    int* __restrict__ perm) {
    __shared__ float skey[4096];
    __shared__ int   sidx[4096];
    for (int i = threadIdx.x; i < npad; i += blockDim.x) {
        skey[i] = (i < n) ? score[i] : -INFINITY;
        sidx[i] = i;
    }
    __syncthreads();
    for (int kk = 2; kk <= npad; kk <<= 1) {
        for (int j = kk >> 1; j > 0; j >>= 1) {
            for (int i = threadIdx.x; i < npad; i += blockDim.x) {
                int ixj = i ^ j;
                if (ixj > i) {
                    float a = skey[i], b = skey[ixj];
                    bool sw = ((i & kk) == 0) ? (a < b) : (a > b);
                    if (sw) {
                        skey[i] = b; skey[ixj] = a;
                        int t = sidx[i]; sidx[i] = sidx[ixj]; sidx[ixj] = t;
                    }
                }
            }
            __syncthreads();
        }
    }
    for (int i = threadIdx.x; i < k; i += blockDim.x) perm[i] = sidx[i];
}

__global__ void k_gatherX(const float* __restrict__ h, int C,
                          const int* __restrict__ perm, const float* __restrict__ score,
                          int k, float* __restrict__ out) {
    int i = blockIdx.x * blockDim.x + threadIdx.x;
    if (i >= k * C) return;
    int r = i / C, cc = i - r * C;
    int pr = perm[r];
    out[i] = h[(size_t)pr * C + cc] * score[pr];
}

__global__ void k_scatter_add(float* __restrict__ u, const float* __restrict__ h,
                              const int* __restrict__ perm, int k, int C) {
    int i = blockIdx.x * blockDim.x + threadIdx.x;
    if (i >= k * C) return;
    int r = i / C, cc = i - r * C;
    u[(size_t)perm[r] * C + cc] += h[i];
}

// ---------------- host orchestration ----------------
static void run_sgemm(int M, int N, int K, const float* A, const float* B, float* C) {
    dim3 g((N + 127) / 128, (M + 127) / 128);
    sgemm<<<g, 256>>>(M, N, K, A, B, C);
}

static void run_hgemm(int M, int N, int K, const __nv_bfloat16* A, int lda,
                      const __nv_bfloat16* B, int ldb, float* C, int ldc, int acc) {
    dim3 g(N / 128, M / 128);
    hgemm<<<g, 256>>>(M, N, K, A, lda, B, ldb, C, ldc, acc);
}

// GCN, exact-bf16 adjacency path: out = act(dis .* ((A+I)@(dis.*xw)) + b)
static void run_gcn_exact(const float* Afp, const __nv_bfloat16* bApI, int n, int np,
                          const float* X, int inC, const float* W, int outC, const float* b,
                          float* out, int act,
                          float* xw, float* t, float* dis,
                          __nv_bfloat16* zh, __nv_bfloat16* zl) {
    run_sgemm(n, outC, inC, X, W, xw);
    k_dis<<<n, 256>>>(Afp, n, dis);
    int Cpad = (outC % 128 == 0) ? outC : 128;
    int tot = np * Cpad;
    k_scale_pair<<<(tot + 255) / 256, 256>>>(xw, dis, n, np, outC, Cpad, zh, zl);
    run_hgemm(np, Cpad, np, bApI, np, zh, Cpad, t, Cpad, 0);
    run_hgemm(np, Cpad, np, bApI, np, zl, Cpad, t, Cpad, 1);
    int nc = n * outC;
    k_epilogue2<<<(nc + 255) / 256, 256>>>(t, Cpad, dis, b, n, outC, out, act);
}

// GCN, split-adjacency path
static void run_gcn_split(const float* Afp, const __nv_bfloat16* X2, int n, int np,
                          const float* X, int inC, const float* W, int outC, const float* b,
                          float* out, int act,
                          float* xw, float* t, float* dis,
                          __nv_bfloat16* zs1, __nv_bfloat16* zs2) {
    run_sgemm(n, outC, inC, X, W, xw);
    k_dis<<<n, 256>>>(Afp, n, dis);
    int tot = np * outC;
    k_scale_pair_stk<<<(tot + 255) / 256, 256>>>(xw, dis, n, np, outC, zs1, zs2);
    run_hgemm(np, outC, 2 * np, X2, 2 * np, zs1, outC, t, outC, 0);
    run_hgemm(np, outC, 2 * np, X2, 2 * np, zs2, outC, t, outC, 1);
    int nc = n * outC;
    k_epilogue2<<<(nc + 255) / 256, 256>>>(t, outC, dis, b, n, outC, out, act);
}

// scores + sort only
static void run_scores_sort(const float* h, int n, int npad, const float* p, int k,
                            int* perm, float* score, float* pn) {
    k_pnorm<<<1, 256>>>(p, HC, pn);
    k_scores<<<(n + 7) / 8, 256>>>(h, n, HC, p, pn, score);
    k_sort_topk<<<1, 1024>>>(score, n, npad, k, perm);
}

extern "C" void kernel_launch(void* const* d_in, const int* in_sizes, int n_in,
                              void* d_out, int out_size) {
    const float* x   = (const float*)d_in[0];
    const int*   ei  = (const int*)  d_in[1];
    const float* Wd0 = (const float*)d_in[2];  const float* bd0 = (const float*)d_in[3];
    const float* Wd1 = (const float*)d_in[4];  const float* bd1 = (const float*)d_in[5];
    const float* Wd2 = (const float*)d_in[6];  const float* bd2 = (const float*)d_in[7];
    const float* Wd3 = (const float*)d_in[8];  const float* bd3 = (const float*)d_in[9];
    const float* p1  = (const float*)d_in[10];
    const float* p2  = (const float*)d_in[11];
    const float* p3  = (const float*)d_in[12];
    const float* Wu0 = (const float*)d_in[13]; const float* bu0 = (const float*)d_in[14];
    const float* Wu1 = (const float*)d_in[15]; const float* bu1 = (const float*)d_in[16];
    const float* Wu2 = (const float*)d_in[17]; const float* bu2 = (const float*)d_in[18];
    const int E = in_sizes[1] / 2;

    float *A0, *Augp, *A1, *A2, *A3, *h0, *h1, *h2, *h3, *hb;
    float *xw, *t, *u, *dis, *sc, *pn;
    int *pm0, *pm1, *pm2;
    __nv_bfloat16 *bA0, *bA1, *bX2, *bX3, *G, *Gt, *Y2, *bzh, *bzl, *bzs1, *bzs2;
    cudaGetSymbolAddress((void**)&A0,  g_A0);
    cudaGetSymbolAddress((void**)&Augp, g_Augp);
    cudaGetSymbolAddress((void**)&A1,  g_A1);
    cudaGetSymbolAddress((void**)&A2,  g_A2);
    cudaGetSymbolAddress((void**)&A3,  g_A3);
    cudaGetSymbolAddress((void**)&h0,  g_h0);
    cudaGetSymbolAddress((void**)&h1,  g_h1);
    cudaGetSymbolAddress((void**)&h2,  g_h2);
    cudaGetSymbolAddress((void**)&h3,  g_h3);
    cudaGetSymbolAddress((void**)&hb,  g_hb);
    cudaGetSymbolAddress((void**)&xw,  g_xw);
    cudaGetSymbolAddress((void**)&t,   g_t);
    cudaGetSymbolAddress((void**)&u,   g_u);
    cudaGetSymbolAddress((void**)&dis, g_dis);
    cudaGetSymbolAddress((void**)&sc,  g_sc);
    cudaGetSymbolAddress((void**)&pn,  g_pn);
    cudaGetSymbolAddress((void**)&pm0, g_perm0);
    cudaGetSymbolAddress((void**)&pm1, g_perm1);
    cudaGetSymbolAddress((void**)&pm2, g_perm2);
    cudaGetSymbolAddress((void**)&bA0, g_bA0);
    cudaGetSymbolAddress((void**)&bA1, g_bA1);
    cudaGetSymbolAddress((void**)&bX2, g_bX2);
    cudaGetSymbolAddress((void**)&bX3, g_bX3);
    cudaGetSymbolAddress((void**)&G,   g_G);
    cudaGetSymbolAddress((void**)&Gt,  g_Gt);
    cudaGetSymbolAddress((void**)&Y2,  g_Y2);
    cudaGetSymbolAddress((void**)&bzh, g_bzh);
    cudaGetSymbolAddress((void**)&bzl, g_bzl);
    cudaGetSymbolAddress((void**)&bzs1, g_bzs1);
    cudaGetSymbolAddress((void**)&bzs2, g_bzs2);

    // ---- build dense adjacency ----
    cudaMemsetAsync(A0, 0, (size_t)N0 * N0 * sizeof(float), 0);
    k_edges<<<(E + 255) / 256, 256>>>(ei, E, A0);
    k_tobf16_adj<<<(N0 * N0 + 255) / 256, 256>>>(A0, N0, N0, bA0);   // bf16(A0+I), exact

    // ---- down path ----
    run_gcn_exact(A0, bA0, N0, 4096, x, INC, Wd0, HC, bd0, h0, ACT_RELU,
                  xw, t, dis, bzh, bzl);

    // pool0: perm first, then augment only the kept submatrix:
    // A1 = [(A0+I)^2]_{perm0,perm0} with zero diag  (exact bf16, symmetric gather)
    run_scores_sort(h0, N0, 4096, p1, KP1, pm0, sc, pn);
    k_gather_rows<<<(2048 * 4096 + 255) / 256, 256>>>(bA0, 4096, pm0, KP1, 2048, G);
    k_gather_cols<<<(4096 * 2048 + 255) / 256, 256>>>(bA0, 4096, pm0, KP1, 2048, Gt);
    run_hgemm(2048, 2048, 4096, G, 4096, Gt, 2048, Augp, 2048, 0);
    k_crop_diag<<<(KP1 * KP1 + 255) / 256, 256>>>(Augp, 2048, KP1, A1);
    k_gatherX<<<(KP1 * HC + 255) / 256, 256>>>(h0, HC, pm0, sc, KP1, u);
    k_tobf16_adj<<<(2048 * 2048 + 255) / 256, 256>>>(A1, KP1, 2048, bA1);
    run_gcn_exact(A1, bA1, KP1, 2048, u, HC, Wd1, HC, bd1, h1, ACT_RELU,
                  xw, t, dis, bzh, bzl);

    // pool1: A2 = [(A1+I)^2]_{perm1,perm1}, zero diag (small ints, exact bf16)
    run_scores_sort(h1, KP1, 2048, p2, KP2, pm1, sc, pn);
    k_gather_rows<<<(1024 * 2048 + 255) / 256, 256>>>(bA1, 2048, pm1, KP2, 1024, G);
    k_gather_cols<<<(2048 * 1024 + 255) / 256, 256>>>(bA1, 2048, pm1, KP2, 1024, Gt);
    run_hgemm(1024, 1024, 2048, G, 2048, Gt, 1024, Augp, 1024, 0);
    k_crop_diag<<<(KP2 * KP2 + 255) / 256, 256>>>(Augp, 1024, KP2, A2);
    k_gatherX<<<(KP2 * HC + 255) / 256, 256>>>(h1, HC, pm1, sc, KP2, u);
    k_pack_X<<<(1024 * 1024 + 255) / 256, 256>>>(A2, KP2, 1024, bX2);
    run_gcn_split(A2, bX2, KP2, 1024, u, HC, Wd2, HC, bd2, h2, ACT_RELU,
                  xw, t, dis, bzs1, bzs2);

    // pool2: A3 = [(A2+I)^2]_{perm2,perm2}, zero diag (exact hi/lo split)
    run_scores_sort(h2, KP2, 1024, p3, KP3, pm2, sc, pn);
    k_gather_rows_split<<<(512 * 1024 + 255) / 256, 256>>>(A2, KP2, 1024, pm2, KP3, 512, G);
    k_gather_cols_split<<<(1024 * 512 + 255) / 256, 256>>>(A2, KP2, 1024, pm2, KP3, 512, Gt, Y2);
    run_hgemm(512, 512, 2048, G, 2048, Gt, 512, Augp, 512, 0);
    run_hgemm(512, 512, 2048, G, 2048, Y2, 512, Augp, 512, 1);
    k_crop_diag<<<(KP3 * KP3 + 255) / 256, 256>>>(Augp, 512, KP3, A3);
    k_gatherX<<<(KP3 * HC + 255) / 256, 256>>>(h2, HC, pm2, sc, KP3, u);
    k_pack_X<<<(512 * 512 + 255) / 256, 256>>>(A3, KP3, 512, bX3);
    run_gcn_split(A3, bX3, KP3, 512, u, HC, Wd3, HC, bd3, h3, ACT_RELU,
                  xw, t, dis, bzs1, bzs2);

    // ---- up path ----
    cudaMemcpyAsync(u, h2, (size_t)KP2 * HC * sizeof(float), cudaMemcpyDeviceToDevice, 0);
    k_scatter_add<<<(KP3 * HC + 255) / 256, 256>>>(u, h3, pm2, KP3, HC);
    run_gcn_split(A2, bX2, KP2, 1024, u, HC, Wu0, HC, bu0, hb, ACT_RELU,
                  xw, t, dis, bzs1, bzs2);

    cudaMemcpyAsync(u, h1, (size_t)KP1 * HC * sizeof(float), cudaMemcpyDeviceToDevice, 0);
    k_scatter_add<<<(KP2 * HC + 255) / 256, 256>>>(u, hb, pm1, KP2, HC);
    run_gcn_exact(A1, bA1, KP1, 2048, u, HC, Wu1, HC, bu1, hb, ACT_RELU,
                  xw, t, dis, bzh, bzl);

    cudaMemcpyAsync(u, h0, (size_t)N0 * HC * sizeof(float), cudaMemcpyDeviceToDevice, 0);
    k_scatter_add<<<(KP1 * HC + 255) / 256, 256>>>(u, hb, pm0, KP1, HC);
    run_gcn_exact(A0, bA0, N0, 4096, u, HC, Wu2, OC, bu2, (float*)d_out, ACT_SIGM,
                  xw, t, dis, bzh, bzl);
}

// round 6
// speedup vs baseline: 4.4284x; 1.2743x over previous
#include <cuda_runtime.h>
#include <cuda_bf16.h>
#include <cstdint>
#include <math.h>

// ---------------- problem constants ----------------
#define N0   4096
#define INC  128
#define HC   512
#define OC   64
#define KP1  2000
#define KP2  1000
#define KP3  500

#define ACT_NONE 0
#define ACT_RELU 1
#define ACT_SIGM 2

// ---------------- scratch (device globals; allocation-free) ----------------
__device__ float g_A0 [(size_t)N0*N0];
__device__ float g_Augp[(size_t)2048*2048];
__device__ float g_A1 [(size_t)KP1*KP1];
__device__ float g_A2 [(size_t)KP2*KP2];
__device__ float g_A3 [(size_t)KP3*KP3];
__device__ float g_h0 [(size_t)N0*HC];
__device__ float g_h1 [(size_t)KP1*HC];
__device__ float g_h2 [(size_t)KP2*HC];
__device__ float g_h3 [(size_t)KP3*HC];
__device__ float g_hb [(size_t)KP1*HC];
__device__ float g_xw [(size_t)N0*HC];
__device__ float g_t  [(size_t)4096*1024];   // packed GEMM output (fp32)
__device__ float g_u  [(size_t)N0*HC];
__device__ float g_dis[N0];
__device__ float g_sc [N0];
__device__ float g_pn [1];
__device__ int   g_perm0[KP1];
__device__ int   g_perm1[KP2];
__device__ int   g_perm2[KP3];
__device__ __nv_bfloat16 g_bA0 [(size_t)4096*4096];  // bf16(A0+I)
__device__ __nv_bfloat16 g_bA1 [(size_t)2048*2048];  // bf16(A1+I)
__device__ __nv_bfloat16 g_bX2 [(size_t)1024*2048];  // (A2+I) split [hi|lo]
__device__ __nv_bfloat16 g_bX3 [(size_t)512*1024];   // (A3+I) split [hi|lo]
__device__ __nv_bfloat16 g_G  [(size_t)2048*4096];   // row-gathered operand
__device__ __nv_bfloat16 g_Q  [(size_t)512*2048];    // pool2 [lo|hi] operand
__device__ __nv_bfloat16 g_zpk[(size_t)4096*1024];   // packed z operand

// ---------------- cp.async helpers ----------------
#define CPASYNC16(dst_u32, src_ptr) \
    asm volatile("cp.async.ca.shared.global [%0], [%1], 16;" :: "r"(dst_u32), "l"(src_ptr))
#define CP_COMMIT() asm volatile("cp.async.commit_group;")

// acc: 0 = store, 1 = non-atomic +=, 2 = atomicAdd (C pre-zeroed; for split-K)
// K-range per block: [z*K/gridDim.z, (z+1)*K/gridDim.z), must be mult of 32.

// ---------------- NN GEMM: C(MxN) = A(MxK) @ B(KxN), bf16->fp32 ----------------
__global__ void __launch_bounds__(256) hgemm_nn(int M, int N, int K,
        const __nv_bfloat16* __restrict__ A, int lda,
        const __nv_bfloat16* __restrict__ B, int ldb,
        float* __restrict__ C, int ldc, int acc) {
    __shared__ __nv_bfloat16 As[2][128][40];
    __shared__ __nv_bfloat16 Bs[2][32][136];
    const int tid  = threadIdx.x;
    const int lane = tid & 31;
    const int warp = tid >> 5;
    const int wm = (warp >> 2) * 64;
    const int wn = (warp & 3) * 32;
    const int m0 = blockIdx.y * 128;
    const int n0 = blockIdx.x * 128;
    const int Kc = K / gridDim.z;
    const int k0 = blockIdx.z * Kc;

    const int ar = tid >> 1, ac = (tid & 1) * 16;
    const int br = tid >> 3, bc = (tid & 7) * 16;

    float c[4][4][4];
#pragma unroll
    for (int mt = 0; mt < 4; mt++)
#pragma unroll
        for (int nt = 0; nt < 4; nt++)
#pragma unroll
            for (int r = 0; r < 4; r++) c[mt][nt][r] = 0.f;

    const int ntile = Kc >> 5;
    {
        unsigned da = (unsigned)__cvta_generic_to_shared(&As[0][ar][ac]);
        const __nv_bfloat16* pa = A + (size_t)(m0 + ar) * lda + k0 + ac;
        CPASYNC16(da, pa); CPASYNC16(da + 16, pa + 8);
        unsigned db = (unsigned)__cvta_generic_to_shared(&Bs[0][br][bc]);
        const __nv_bfloat16* pb = B + (size_t)(k0 + br) * ldb + n0 + bc;
        CPASYNC16(db, pb); CPASYNC16(db + 16, pb + 8);
        CP_COMMIT();
    }

    for (int it = 0; it < ntile; ++it) {
        if (it + 1 < ntile) {
            int s = (it + 1) & 1, kk = k0 + ((it + 1) << 5);
            unsigned da = (unsigned)__cvta_generic_to_shared(&As[s][ar][ac]);
            const __nv_bfloat16* pa = A + (size_t)(m0 + ar) * lda + kk + ac;
            CPASYNC16(da, pa); CPASYNC16(da + 16, pa + 8);
            unsigned db = (unsigned)__cvta_generic_to_shared(&Bs[s][br][bc]);
            const __nv_bfloat16* pb = B + (size_t)(kk + br) * ldb + n0 + bc;
            CPASYNC16(db, pb); CPASYNC16(db + 16, pb + 8);
            CP_COMMIT();
            asm volatile("cp.async.wait_group 1;");
        } else {
            asm volatile("cp.async.wait_group 0;");
        }
        __syncthreads();

        const int s = it & 1;
#pragma unroll
        for (int ks = 0; ks < 32; ks += 16) {
            uint32_t af[4][4];
#pragma unroll
            for (int mt = 0; mt < 4; mt++) {
                unsigned addr = (unsigned)__cvta_generic_to_shared(
                    &As[s][wm + mt * 16 + (lane & 15)][ks + (lane >> 4) * 8]);
                asm volatile("ldmatrix.sync.aligned.m8n8.x4.shared.b16 {%0,%1,%2,%3}, [%4];"
                    : "=r"(af[mt][0]), "=r"(af[mt][1]), "=r"(af[mt][2]), "=r"(af[mt][3])
                    : "r"(addr));
            }
            uint32_t bfr[4][2];
#pragma unroll
            for (int nt = 0; nt < 4; nt++) {
                unsigned addr = (unsigned)__cvta_generic_to_shared(
                    &Bs[s][ks + (lane & 15)][wn + nt * 8]);
                asm volatile("ldmatrix.sync.aligned.m8n8.x2.trans.shared.b16 {%0,%1}, [%2];"
                    : "=r"(bfr[nt][0]), "=r"(bfr[nt][1]) : "r"(addr));
            }
#pragma unroll
            for (int mt = 0; mt < 4; mt++)
#pragma unroll
                for (int nt = 0; nt < 4; nt++)
                    asm volatile(
                        "mma.sync.aligned.m16n8k16.row.col.f32.bf16.bf16.f32 "
                        "{%0,%1,%2,%3}, {%4,%5,%6,%7}, {%8,%9}, {%0,%1,%2,%3};"
                        : "+f"(c[mt][nt][0]), "+f"(c[mt][nt][1]),
                          "+f"(c[mt][nt][2]), "+f"(c[mt][nt][3])
                        : "r"(af[mt][0]), "r"(af[mt][1]), "r"(af[mt][2]), "r"(af[mt][3]),
                          "r"(bfr[nt][0]), "r"(bfr[nt][1]));
        }
        __syncthreads();
    }

    const int r0 = lane >> 2, c0 = (lane & 3) * 2;
#pragma unroll
    for (int mt = 0; mt < 4; mt++)
#pragma unroll
        for (int nt = 0; nt < 4; nt++) {
            int row = m0 + wm + mt * 16 + r0;
            int col = n0 + wn + nt * 8 + c0;
            float* p0 = C + (size_t)row * ldc + col;
            float* p1 = C + (size_t)(row + 8) * ldc + col;
            if (acc == 2) {
                atomicAdd(p0,     c[mt][nt][0]); atomicAdd(p0 + 1, c[mt][nt][1]);
                atomicAdd(p1,     c[mt][nt][2]); atomicAdd(p1 + 1, c[mt][nt][3]);
            } else if (acc == 1) {
                p0[0] += c[mt][nt][0]; p0[1] += c[mt][nt][1];
                p1[0] += c[mt][nt][2]; p1[1] += c[mt][nt][3];
            } else {
                p0[0] = c[mt][nt][0]; p0[1] = c[mt][nt][1];
                p1[0] = c[mt][nt][2]; p1[1] = c[mt][nt][3];
            }
        }
}

// ---------------- NT GEMM: C(MxN) = A(MxK) @ B(NxK)^T, bf16->fp32 ----------------
__global__ void __launch_bounds__(256) hgemm_nt(int M, int N, int K,
        const __nv_bfloat16* __restrict__ A, int lda,
        const __nv_bfloat16* __restrict__ B, int ldb,
        float* __restrict__ C, int ldc, int acc) {
    __shared__ __nv_bfloat16 As[2][128][40];
    __shared__ __nv_bfloat16 Bs[2][128][40];
    const int tid  = threadIdx.x;
    const int lane = tid & 31;
    const int warp = tid >> 5;
    const int wm = (warp >> 2) * 64;
    const int wn = (warp & 3) * 32;
    const int m0 = blockIdx.y * 128;
    const int n0 = blockIdx.x * 128;
    const int Kc = K / gridDim.z;
    const int k0 = blockIdx.z * Kc;

    const int ar = tid >> 1, ac = (tid & 1) * 16;

    float c[4][4][4];
#pragma unroll
    for (int mt = 0; mt < 4; mt++)
#pragma unroll
        for (int nt = 0; nt < 4; nt++)
#pragma unroll
            for (int r = 0; r < 4; r++) c[mt][nt][r] = 0.f;

    const int ntile = Kc >> 5;
    {
        unsigned da = (unsigned)__cvta_generic_to_shared(&As[0][ar][ac]);
        const __nv_bfloat16* pa = A + (size_t)(m0 + ar) * lda + k0 + ac;
        CPASYNC16(da, pa); CPASYNC16(da + 16, pa + 8);
        unsigned db = (unsigned)__cvta_generic_to_shared(&Bs[0][ar][ac]);
        const __nv_bfloat16* pb = B + (size_t)(n0 + ar) * ldb + k0 + ac;
        CPASYNC16(db, pb); CPASYNC16(db + 16, pb + 8);
        CP_COMMIT();
    }

    for (int it = 0; it < ntile; ++it) {
        if (it + 1 < ntile) {
            int s = (it + 1) & 1, kk = k0 + ((it + 1) << 5);
            unsigned da = (unsigned)__cvta_generic_to_shared(&As[s][ar][ac]);
            const __nv_bfloat16* pa = A + (size_t)(m0 + ar) * lda + kk + ac;
            CPASYNC16(da, pa); CPASYNC16(da + 16, pa + 8);
            unsigned db = (unsigned)__cvta_generic_to_shared(&Bs[s][ar][ac]);
            const __nv_bfloat16* pb = B + (size_t)(n0 + ar) * ldb + kk + ac;
            CPASYNC16(db, pb); CPASYNC16(db + 16, pb + 8);
            CP_COMMIT();
            asm volatile("cp.async.wait_group 1;");
        } else {
            asm volatile("cp.async.wait_group 0;");
        }
        __syncthreads();

        const int s = it & 1;
#pragma unroll
        for (int ks = 0; ks < 32; ks += 16) {
            uint32_t af[4][4];
#pragma unroll
            for (int mt = 0; mt < 4; mt++) {
                unsigned addr = (unsigned)__cvta_generic_to_shared(
                    &As[s][wm + mt * 16 + (lane & 15)][ks + (lane >> 4) * 8]);
                asm volatile("ldmatrix.sync.aligned.m8n8.x4.shared.b16 {%0,%1,%2,%3}, [%4];"
                    : "=r"(af[mt][0]), "=r"(af[mt][1]), "=r"(af[mt][2]), "=r"(af[mt][3])
                    : "r"(addr));
            }
            uint32_t bfr[4][2];
#pragma unroll
            for (int nt = 0; nt < 4; nt++) {
                // non-trans ldmatrix on n-major tile -> col-major B fragment
                unsigned addr = (unsigned)__cvta_generic_to_shared(
                    &Bs[s][wn + nt * 8 + (lane & 7)][ks + ((lane >> 3) & 1) * 8]);
                asm volatile("ldmatrix.sync.aligned.m8n8.x2.shared.b16 {%0,%1}, [%2];"
                    : "=r"(bfr[nt][0]), "=r"(bfr[nt][1]) : "r"(addr));
            }
#pragma unroll
            for (int mt = 0; mt < 4; mt++)
#pragma unroll
                for (int nt = 0; nt < 4; nt++)
                    asm volatile(
                        "mma.sync.aligned.m16n8k16.row.col.f32.bf16.bf16.f32 "
                        "{%0,%1,%2,%3}, {%4,%5,%6,%7}, {%8,%9}, {%0,%1,%2,%3};"
                        : "+f"(c[mt][nt][0]), "+f"(c[mt][nt][1]),
                          "+f"(c[mt][nt][2]), "+f"(c[mt][nt][3])
                        : "r"(af[mt][0]), "r"(af[mt][1]), "r"(af[mt][2]), "r"(af[mt][3]),
                          "r"(bfr[nt][0]), "r"(bfr[nt][1]));
        }
        __syncthreads();
    }

    const int r0 = lane >> 2, c0 = (lane & 3) * 2;
#pragma unroll
    for (int mt = 0; mt < 4; mt++)
#pragma unroll
        for (int nt = 0; nt < 4; nt++) {
            int row = m0 + wm + mt * 16 + r0;
            int col = n0 + wn + nt * 8 + c0;
            float* p0 = C + (size_t)row * ldc + col;
            float* p1 = C + (size_t)(row + 8) * ldc + col;
            if (acc == 2) {
                atomicAdd(p0,     c[mt][nt][0]); atomicAdd(p0 + 1, c[mt][nt][1]);
                atomicAdd(p1,     c[mt][nt][2]); atomicAdd(p1 + 1, c[mt][nt][3]);
            } else if (acc == 1) {
                p0[0] += c[mt][nt][0]; p0[1] += c[mt][nt][1];
                p1[0] += c[mt][nt][2]; p1[1] += c[mt][nt][3];
            } else {
                p0[0] = c[mt][nt][0]; p0[1] = c[mt][nt][1];
                p1[0] = c[mt][nt][2]; p1[1] = c[mt][nt][3];
            }
        }
}

// ---------------- SGEMM (fp32 SIMT) for X@W ----------------
__global__ void __launch_bounds__(256) sgemm(int M, int N, int K,
                                             const float* __restrict__ A,
                                             const float* __restrict__ B,
                                             float* __restrict__ C) {
    __shared__ float As[8][128];
    __shared__ float Bs[8][128];
    const int tid  = threadIdx.x;
    const int tx   = tid & 15;
    const int ty   = tid >> 4;
    const int row0 = blockIdx.y * 128;
    const int col0 = blockIdx.x * 128;
    const int a_row = tid >> 1, a_col = (tid & 1) << 2;
    const int b_row = tid >> 5, b_col = (tid & 31) << 2;

    float acc[8][8];
#pragma unroll
    for (int i = 0; i < 8; i++)
#pragma unroll
        for (int j = 0; j < 8; j++) acc[i][j] = 0.f;

    for (int kk = 0; kk < K; kk += 8) {
        float4 av = make_float4(0.f, 0.f, 0.f, 0.f);
        {
            int gm = row0 + a_row, gk = kk + a_col;
            if (gm < M && gk < K)
                av = *reinterpret_cast<const float4*>(A + (size_t)gm * K + gk);
        }
        As[a_col + 0][a_row] = av.x;
        As[a_col + 1][a_row] = av.y;
        As[a_col + 2][a_row] = av.z;
        As[a_col + 3][a_row] = av.w;

        float4 bv = make_float4(0.f, 0.f, 0.f, 0.f);
        {
            int gk = kk + b_row, gn = col0 + b_col;
            if (gk < K && gn < N)
                bv = *reinterpret_cast<const float4*>(B + (size_t)gk * N + gn);
        }
        *reinterpret_cast<float4*>(&Bs[b_row][b_col]) = bv;
        __syncthreads();

#pragma unroll
        for (int k = 0; k < 8; k++) {
            float4 a0 = *reinterpret_cast<const float4*>(&As[k][ty * 8]);
            float4 a1 = *reinterpret_cast<const float4*>(&As[k][ty * 8 + 4]);
            float4 b0 = *reinterpret_cast<const float4*>(&Bs[k][tx * 8]);
            float4 b1 = *reinterpret_cast<const float4*>(&Bs[k][tx * 8 + 4]);
            float a[8] = {a0.x, a0.y, a0.z, a0.w, a1.x, a1.y, a1.z, a1.w};
            float b[8] = {b0.x, b0.y, b0.z, b0.w, b1.x, b1.y, b1.z, b1.w};
#pragma unroll
            for (int i = 0; i < 8; i++)
#pragma unroll
                for (int j = 0; j < 8; j++) acc[i][j] += a[i] * b[j];
        }
        __syncthreads();
    }

#pragma unroll
    for (int i = 0; i < 8; i++) {
        int gm = row0 + ty * 8 + i;
        if (gm >= M) continue;
        float* Cr = C + (size_t)gm * N;
#pragma unroll
        for (int j = 0; j < 8; j++) {
            int gn = col0 + tx * 8 + j;
            if (gn < N) Cr[gn] = acc[i][j];
        }
    }
}

// ---------------- elementwise / graph kernels ----------------
__global__ void k_edges(const int* __restrict__ ei, int E, float* __restrict__ A) {
    int e = blockIdx.x * blockDim.x + threadIdx.x;
    if (e >= E) return;
    int s = ei[e], d = ei[E + e];
    A[(size_t)s * N0 + d] = 1.f;
    A[(size_t)d * N0 + s] = 1.f;
}

__global__ void k_dis(const float* __restrict__ A, int n, float* __restrict__ dis) {
    __shared__ float red[256];
    int row = blockIdx.x;
    const float* Ar = A + (size_t)row * n;
    float s = 0.f;
    for (int j = threadIdx.x; j < n; j += 256) s += Ar[j];
    red[threadIdx.x] = s;
    __syncthreads();
    for (int o = 128; o > 0; o >>= 1) {
        if (threadIdx.x < o) red[threadIdx.x] += red[threadIdx.x + o];
        __syncthreads();
    }
    if (threadIdx.x == 0) dis[row] = rsqrtf(red[0] + 1.0f);
}

// packed z: zpk (np x 2Cpad) = [hi(dis*xw) | lo(dis*xw)]
__global__ void k_scale_pack(const float* __restrict__ xw, const float* __restrict__ dis,
                             int n, int np, int C, int Cpad,
                             __nv_bfloat16* __restrict__ zpk) {
    int i = blockIdx.x * blockDim.x + threadIdx.x;
    int W = 2 * Cpad;
    if (i >= np * W) return;
    int r = i / W, cc = i - r * W;
    int col = (cc < Cpad) ? cc : cc - Cpad;
    float v = (r < n && col < C) ? dis[r] * xw[(size_t)r * C + col] : 0.f;
    __nv_bfloat16 hi = __float2bfloat16(v);
    if (cc < Cpad) zpk[i] = hi;
    else           zpk[i] = __float2bfloat16(v - __bfloat162float(hi));
}

// packed stacked z: Bp (2np x 2C); rows<np: [hi|lo], rows>=np: [lo|hi]
__global__ void k_scale_pack_stk(const float* __restrict__ xw, const float* __restrict__ dis,
                                 int n, int np, int C,
                                 __nv_bfloat16* __restrict__ Bp) {
    int i = blockIdx.x * blockDim.x + threadIdx.x;
    int W = 2 * C;
    if (i >= 2 * np * W) return;
    int r = i / W, cc = i - r * W;
    int rr = (r < np) ? r : r - np;
    int col = (cc < C) ? cc : cc - C;
    float v = (rr < n) ? dis[rr] * xw[(size_t)rr * C + col] : 0.f;
    __nv_bfloat16 hi = __float2bfloat16(v);
    __nv_bfloat16 lo = __float2bfloat16(v - __bfloat162float(hi));
    bool wantHi = ((r < np) == (cc < C));   // top-left and bottom-right are hi
    Bp[i] = wantHi ? hi : lo;
}

// out = act(dis*(t[cc] + t[cc+half]) + b)
__global__ void k_epilogue_sum2(const float* __restrict__ t, int ldt, int half,
                                const float* __restrict__ dis, const float* __restrict__ b,
                                int n, int C, float* __restrict__ out, int act) {
    int i = blockIdx.x * blockDim.x + threadIdx.x;
    if (i >= n * C) return;
    int r = i / C, cc = i - r * C;
    float v = dis[r] * (t[(size_t)r * ldt + cc] + t[(size_t)r * ldt + cc + half]) + b[cc];
    if (act == ACT_RELU) v = fmaxf(v, 0.f);
    else if (act == ACT_SIGM) v = 1.f / (1.f + expf(-v));
    out[i] = v;
}

__global__ void k_tobf16_adj(const float* __restrict__ A, int n, int np,
                             __nv_bfloat16* __restrict__ out) {
    int i = blockIdx.x * blockDim.x + threadIdx.x;
    if (i >= np * np) return;
    int r = i / np, cc = i - r * np;
    float v = 0.f;
    if (r < n && cc < n) v = A[(size_t)r * n + cc] + (r == cc ? 1.f : 0.f);
    out[i] = __float2bfloat16(v);
}

__global__ void k_pack_X(const float* __restrict__ A, int n, int np,
                         __nv_bfloat16* __restrict__ X) {
    int i = blockIdx.x * blockDim.x + threadIdx.x;
    if (i >= np * np) return;
    int r = i / np, cc = i - r * np;
    float v = 0.f;
    if (r < n && cc < n) v = A[(size_t)r * n + cc] + (r == cc ? 1.f : 0.f);
    __nv_bfloat16 hi = __float2bfloat16(v);
    __nv_bfloat16 lo = __float2bfloat16(v - __bfloat162float(hi));
    X[(size_t)r * (2 * np) + cc]      = hi;
    X[(size_t)r * (2 * np) + np + cc] = lo;
}

// G[r][:] = bApI[perm[r]][:]  (kpad x np)
__global__ void k_gather_rows(const __nv_bfloat16* __restrict__ bApI, int np,
                              const int* __restrict__ perm, int k, int kpad,
                              __nv_bfloat16* __restrict__ G) {
    int i = blockIdx.x * blockDim.x + threadIdx.x;
    if (i >= kpad * np) return;
    int r = i / np, j = i - r * np;
    G[i] = (r < k) ? bApI[(size_t)perm[r] * np + j] : __float2bfloat16(0.f);
}

// pool2 operands: P=[hi|lo], Q=[lo|hi] of (A+I)[perm[r]][:]  (kpad x 2np each)
__global__ void k_gather_rows_PQ(const float* __restrict__ A, int n, int np,
                                 const int* __restrict__ perm, int k, int kpad,
                                 __nv_bfloat16* __restrict__ P,
                                 __nv_bfloat16* __restrict__ Q) {
    int i = blockIdx.x * blockDim.x + threadIdx.x;
    if (i >= kpad * np) return;
    int r = i / np, j = i - r * np;
    float v = 0.f;
    if (r < k && j < n) {
        int pr = perm[r];
        v = A[(size_t)pr * n + j] + (pr == j ? 1.f : 0.f);
    }
    __nv_bfloat16 hi = __float2bfloat16(v);
    __nv_bfloat16 lo = __float2bfloat16(v - __bfloat162float(hi));
    P[(size_t)r * (2 * np) + j]      = hi;
    P[(size_t)r * (2 * np) + np + j] = lo;
    Q[(size_t)r * (2 * np) + j]      = lo;
    Q[(size_t)r * (2 * np) + np + j] = hi;
}

__global__ void k_crop_diag(const float* __restrict__ Augp, int kpad, int k,
                            float* __restrict__ Adst) {
    int i = blockIdx.x * blockDim.x + threadIdx.x;
    if (i >= k * k) return;
    int r = i / k, cc = i - r * k;
    Adst[i] = (r == cc) ? 0.f : Augp[(size_t)r * kpad + cc];
}

__global__ void k_pnorm(const float* __restrict__ p, int n, float* __restrict__ out) {
    __shared__ float red[256];
    float s = 0.f;
    for (int i = threadIdx.x; i < n; i += 256) s += p[i] * p[i];
    red[threadIdx.x] = s;
    __syncthreads();
    for (int o = 128; o > 0; o >>= 1) {
        if (threadIdx.x < o) red[threadIdx.x] += red[threadIdx.x + o];
        __syncthreads();
    }
    if (threadIdx.x == 0) out[0] = sqrtf(red[0]);
}

__global__ void k_scores(const float* __restrict__ h, int n, int C,
                         const float* __restrict__ p, const float* __restrict__ pn,
                         float* __restrict__ score) {
    int row = blockIdx.x * 8 + (threadIdx.x >> 5);
    int lane = threadIdx.x & 31;
    if (row >= n) return;
    const float* hr = h + (size_t)row * C;
    float s = 0.f;
    for (int cc = lane; cc < C; cc += 32) s += hr[cc] * p[cc];
    for (int o = 16; o > 0; o >>= 1) s += __shfl_xor_sync(0xffffffffu, s, o);
    if (lane == 0) score[row] = tanhf(s / pn[0]);
}

__global__ void __launch_bounds__(1024) k_sort_topk(const float* __restrict__ score,
                                                    int n, int npad, int k,
                                                    int* __restrict__ perm) {
    __shared__ float skey[4096];
    __shared__ int   sidx[4096];
    for (int i = threadIdx.x; i < npad; i += blockDim.x) {
        skey[i] = (i < n) ? score[i] : -INFINITY;
        sidx[i] = i;
    }
    __syncthreads();
    for (int kk = 2; kk <= npad; kk <<= 1) {
        for (int j = kk >> 1; j > 0; j >>= 1) {
            for (int i = threadIdx.x; i < npad; i += blockDim.x) {
                int ixj = i ^ j;
                if (ixj > i) {
                    float a = skey[i], b = skey[ixj];
                    bool sw = ((i & kk) == 0) ? (a < b) : (a > b);
                    if (sw) {
                        skey[i] = b; skey[ixj] = a;
                        int t = sidx[i]; sidx[i] = sidx[ixj]; sidx[ixj] = t;
                    }
                }
            }
            __syncthreads();
        }
    }
    for (int i = threadIdx.x; i < k; i += blockDim.x) perm[i] = sidx[i];
}

__global__ void k_gatherX(const float* __restrict__ h, int C,
                          const int* __restrict__ perm, const float* __restrict__ score,
                          int k, float* __restrict__ out) {
    int i = blockIdx.x * blockDim.x + threadIdx.x;
    if (i >= k * C) return;
    int r = i / C, cc = i - r * C;
    int pr = perm[r];
    out[i] = h[(size_t)pr * C + cc] * score[pr];
}

__global__ void k_scatter_add(float* __restrict__ u, const float* __restrict__ h,
                              const int* __restrict__ perm, int k, int C) {
    int i = blockIdx.x * blockDim.x + threadIdx.x;
    if (i >= k * C) return;
    int r = i / C, cc = i - r * C;
    u[(size_t)perm[r] * C + cc] += h[i];
}

// ---------------- host orchestration ----------------
static void run_sgemm(int M, int N, int K, const float* A, const float* B, float* C) {
    dim3 g((N + 127) / 128, (M + 127) / 128);
    sgemm<<<g, 256>>>(M, N, K, A, B, C);
}
static void run_nn(int M, int N, int K, const __nv_bfloat16* A, int lda,
                   const __nv_bfloat16* B, int ldb, float* C, int ldc, int acc, int splitk) {
    dim3 g(N / 128, M / 128, splitk);
    hgemm_nn<<<g, 256>>>(M, N, K, A, lda, B, ldb, C, ldc, acc);
}
static void run_nt(int M, int N, int K, const __nv_bfloat16* A, int lda,
                   const __nv_bfloat16* B, int ldb, float* C, int ldc, int acc) {
    dim3 g(N / 128, M / 128, 1);
    hgemm_nt<<<g, 256>>>(M, N, K, A, lda, B, ldb, C, ldc, acc);
}

// exact-bf16 adjacency GCN: one packed split-K GEMM
static void run_gcn_exact(const float* Afp, const __nv_bfloat16* bApI, int n, int np,
                          const float* X, int inC, const float* W, int outC, const float* b,
                          float* out, int act, int splitk,
                          float* xw, float* t, float* dis, __nv_bfloat16* zpk) {
    run_sgemm(n, outC, inC, X, W, xw);
    k_dis<<<n, 256>>>(Afp, n, dis);
    int Cpad = (outC % 128 == 0) ? outC : 128;
    int W2 = 2 * Cpad;
    int tot = np * W2;
    k_scale_pack<<<(tot + 255) / 256, 256>>>(xw, dis, n, np, outC, Cpad, zpk);
    cudaMemsetAsync(t, 0, (size_t)np * W2 * sizeof(float), 0);
    run_nn(np, W2, np, bApI, np, zpk, W2, t, W2, 2, splitk);
    int nc = n * outC;
    k_epilogue_sum2<<<(nc + 255) / 256, 256>>>(t, W2, Cpad, dis, b, n, outC, out, act);
}

// split-adjacency GCN: one packed split-K GEMM over stacked K
static void run_gcn_split(const float* Afp, const __nv_bfloat16* X2, int n, int np,
                          const float* X, int inC, const float* W, int outC, const float* b,
                          float* out, int act, int splitk,
                          float* xw, float* t, float* dis, __nv_bfloat16* Bp) {
    run_sgemm(n, outC, inC, X, W, xw);
    k_dis<<<n, 256>>>(Afp, n, dis);
    int W2 = 2 * outC;
    int tot = 2 * np * W2;
    k_scale_pack_stk<<<(tot + 255) / 256, 256>>>(xw, dis, n, np, outC, Bp);
    cudaMemsetAsync(t, 0, (size_t)np * W2 * sizeof(float), 0);
    run_nn(np, W2, 2 * np, X2, 2 * np, Bp, W2, t, W2, 2, splitk);
    int nc = n * outC;
    k_epilogue_sum2<<<(nc + 255) / 256, 256>>>(t, W2, outC, dis, b, n, outC, out, act);
}

static void run_scores_sort(const float* h, int n, int npad, const float* p, int k,
                            int* perm, float* score, float* pn) {
    k_pnorm<<<1, 256>>>(p, HC, pn);
    k_scores<<<(n + 7) / 8, 256>>>(h, n, HC, p, pn, score);
    k_sort_topk<<<1, 1024>>>(score, n, npad, k, perm);
}

extern "C" void kernel_launch(void* const* d_in, const int* in_sizes, int n_in,
                              void* d_out, int out_size) {
    const float* x   = (const float*)d_in[0];
    const int*   ei  = (const int*)  d_in[1];
    const float* Wd0 = (const float*)d_in[2];  const float* bd0 = (const float*)d_in[3];
    const float* Wd1 = (const float*)d_in[4];  const float* bd1 = (const float*)d_in[5];
    const float* Wd2 = (const float*)d_in[6];  const float* bd2 = (const float*)d_in[7];
    const float* Wd3 = (const float*)d_in[8];  const float* bd3 = (const float*)d_in[9];
    const float* p1  = (const float*)d_in[10];
    const float* p2  = (const float*)d_in[11];
    const float* p3  = (const float*)d_in[12];
    const float* Wu0 = (const float*)d_in[13]; const float* bu0 = (const float*)d_in[14];
    const float* Wu1 = (const float*)d_in[15]; const float* bu1 = (const float*)d_in[16];
    const float* Wu2 = (const float*)d_in[17]; const float* bu2 = (const float*)d_in[18];
    const int E = in_sizes[1] / 2;

    float *A0, *Augp, *A1, *A2, *A3, *h0, *h1, *h2, *h3, *hb;
    float *xw, *t, *u, *dis, *sc, *pn;
    int *pm0, *pm1, *pm2;
    __nv_bfloat16 *bA0, *bA1, *bX2, *bX3, *G, *Q, *zpk;
    cudaGetSymbolAddress((void**)&A0,  g_A0);
    cudaGetSymbolAddress((void**)&Augp, g_Augp);
    cudaGetSymbolAddress((void**)&A1,  g_A1);
    cudaGetSymbolAddress((void**)&A2,  g_A2);
    cudaGetSymbolAddress((void**)&A3,  g_A3);
    cudaGetSymbolAddress((void**)&h0,  g_h0);
    cudaGetSymbolAddress((void**)&h1,  g_h1);
    cudaGetSymbolAddress((void**)&h2,  g_h2);
    cudaGetSymbolAddress((void**)&h3,  g_h3);
    cudaGetSymbolAddress((void**)&hb,  g_hb);
    cudaGetSymbolAddress((void**)&xw,  g_xw);
    cudaGetSymbolAddress((void**)&t,   g_t);
    cudaGetSymbolAddress((void**)&u,   g_u);
    cudaGetSymbolAddress((void**)&dis, g_dis);
    cudaGetSymbolAddress((void**)&sc,  g_sc);
    cudaGetSymbolAddress((void**)&pn,  g_pn);
    cudaGetSymbolAddress((void**)&pm0, g_perm0);
    cudaGetSymbolAddress((void**)&pm1, g_perm1);
    cudaGetSymbolAddress((void**)&pm2, g_perm2);
    cudaGetSymbolAddress((void**)&bA0, g_bA0);
    cudaGetSymbolAddress((void**)&bA1, g_bA1);
    cudaGetSymbolAddress((void**)&bX2, g_bX2);
    cudaGetSymbolAddress((void**)&bX3, g_bX3);
    cudaGetSymbolAddress((void**)&G,   g_G);
    cudaGetSymbolAddress((void**)&Q,   g_Q);
    cudaGetSymbolAddress((void**)&zpk, g_zpk);

    // ---- build dense adjacency ----
    cudaMemsetAsync(A0, 0, (size_t)N0 * N0 * sizeof(float), 0);
    k_edges<<<(E + 255) / 256, 256>>>(ei, E, A0);
    k_tobf16_adj<<<(N0 * N0 + 255) / 256, 256>>>(A0, N0, N0, bA0);

    // ---- down path ----
    run_gcn_exact(A0, bA0, N0, 4096, x, INC, Wd0, HC, bd0, h0, ACT_RELU, 4,
                  xw, t, dis, zpk);

    // pool0: A1 = [(A0+I)^2]_{perm0,perm0} = G@G^T, zero diag
    run_scores_sort(h0, N0, 4096, p1, KP1, pm0, sc, pn);
    k_gather_rows<<<(2048 * 4096 + 255) / 256, 256>>>(bA0, 4096, pm0, KP1, 2048, G);
    run_nt(2048, 2048, 4096, G, 4096, G, 4096, Augp, 2048, 0);
    k_crop_diag<<<(KP1 * KP1 + 255) / 256, 256>>>(Augp, 2048, KP1, A1);
    k_gatherX<<<(KP1 * HC + 255) / 256, 256>>>(h0, HC, pm0, sc, KP1, u);
    k_tobf16_adj<<<(2048 * 2048 + 255) / 256, 256>>>(A1, KP1, 2048, bA1);
    run_gcn_exact(A1, bA1, KP1, 2048, u, HC, Wd1, HC, bd1, h1, ACT_RELU, 4,
                  xw, t, dis, zpk);

    // pool1: A2 = [(A1+I)^2]_{perm1,perm1} = G@G^T, zero diag
    run_scores_sort(h1, KP1, 2048, p2, KP2, pm1, sc, pn);
    k_gather_rows<<<(1024 * 2048 + 255) / 256, 256>>>(bA1, 2048, pm1, KP2, 1024, G);
    run_nt(1024, 1024, 2048, G, 2048, G, 2048, Augp, 1024, 0);
    k_crop_diag<<<(KP2 * KP2 + 255) / 256, 256>>>(Augp, 1024, KP2, A2);
    k_gatherX<<<(KP2 * HC + 255) / 256, 256>>>(h1, HC, pm1, sc, KP2, u);
    k_pack_X<<<(1024 * 1024 + 255) / 256, 256>>>(A2, KP2, 1024, bX2);
    run_gcn_split(A2, bX2, KP2, 1024, u, HC, Wd2, HC, bd2, h2, ACT_RELU, 2,
                  xw, t, dis, zpk);

    // pool2: A3 = P@P^T + P@Q^T (exact hi/lo split), zero diag
    run_scores_sort(h2, KP2, 1024, p3, KP3, pm2, sc, pn);
    k_gather_rows_PQ<<<(512 * 1024 + 255) / 256, 256>>>(A2, KP2, 1024, pm2, KP3, 512, G, Q);
    run_nt(512, 512, 2048, G, 2048, G, 2048, Augp, 512, 0);
    run_nt(512, 512, 2048, G, 2048, Q, 2048, Augp, 512, 1);
    k_crop_diag<<<(KP3 * KP3 + 255) / 256, 256>>>(Augp, 512, KP3, A3);
    k_gatherX<<<(KP3 * HC + 255) / 256, 256>>>(h2, HC, pm2, sc, KP3, u);
    k_pack_X<<<(512 * 512 + 255) / 256, 256>>>(A3, KP3, 512, bX3);
    run_gcn_split(A3, bX3, KP3, 512, u, HC, Wd3, HC, bd3, h3, ACT_RELU, 4,
                  xw, t, dis, zpk);

    // ---- up path ----
    cudaMemcpyAsync(u, h2, (size_t)KP2 * HC * sizeof(float), cudaMemcpyDeviceToDevice, 0);
    k_scatter_add<<<(KP3 * HC + 255) / 256, 256>>>(u, h3, pm2, KP3, HC);
    run_gcn_split(A2, bX2, KP2, 1024, u, HC, Wu0, HC, bu0, hb, ACT_RELU, 2,
                  xw, t, dis, zpk);

    cudaMemcpyAsync(u, h1, (size_t)KP1 * HC * sizeof(float), cudaMemcpyDeviceToDevice, 0);
    k_scatter_add<<<(KP2 * HC + 255) / 256, 256>>>(u, hb, pm1, KP2, HC);
    run_gcn_exact(A1, bA1, KP1, 2048, u, HC, Wu1, HC, bu1, hb, ACT_RELU, 4,
                  xw, t, dis, zpk);

    cudaMemcpyAsync(u, h0, (size_t)N0 * HC * sizeof(float), cudaMemcpyDeviceToDevice, 0);
    k_scatter_add<<<(KP1 * HC + 255) / 256, 256>>>(u, hb, pm0, KP1, HC);
    run_gcn_exact(A0, bA0, N0, 4096, u, HC, Wu2, OC, bu2, (float*)d_out, ACT_SIGM, 4,
                  xw, t, dis, zpk);
}

// round 7
// speedup vs baseline: 4.9808x; 1.1247x over previous
#include <cuda_runtime.h>
#include <cuda_bf16.h>
#include <cstdint>
#include <math.h>

// ---------------- problem constants ----------------
#define N0   4096
#define INC  128
#define HC   512
#define OC   64
#define KP1  2000
#define KP2  1000
#define KP3  500

#define ACT_NONE 0
#define ACT_RELU 1
#define ACT_SIGM 2

// ---------------- scratch (device globals; allocation-free) ----------------
__device__ float g_Augp[(size_t)2048*2048];
__device__ float g_h0 [(size_t)N0*HC];
__device__ float g_h1 [(size_t)KP1*HC];
__device__ float g_h2 [(size_t)KP2*HC];
__device__ float g_h3 [(size_t)KP3*HC];
__device__ float g_hb [(size_t)KP1*HC];
__device__ float g_xw [(size_t)N0*HC];
__device__ float g_t  [(size_t)4096*1024];   // packed GEMM output (fp32)
__device__ float g_u  [(size_t)N0*HC];
__device__ float g_dis[N0];
__device__ float g_sc [N0];
__device__ float g_pn [1];
__device__ int   g_perm0[KP1];
__device__ int   g_perm1[KP2];
__device__ int   g_perm2[KP3];
__device__ __nv_bfloat16 g_bA0 [(size_t)4096*4096];  // bf16(A0+I)
__device__ __nv_bfloat16 g_bA1 [(size_t)2048*2048];  // bf16(A1+I)
__device__ __nv_bfloat16 g_bX2 [(size_t)1024*2048];  // (A2+I) split [hi|lo]
__device__ __nv_bfloat16 g_bX3 [(size_t)512*1024];   // (A3+I) split [hi|lo]
__device__ __nv_bfloat16 g_G  [(size_t)2048*4096];   // row-gathered operand / P
__device__ __nv_bfloat16 g_Q  [(size_t)512*2048];    // pool2 [lo|hi] operand
__device__ __nv_bfloat16 g_zpk[(size_t)4096*1024];   // packed z operand

// ---------------- cp.async helpers ----------------
#define CPASYNC16(dst_u32, src_ptr) \
    asm volatile("cp.async.ca.shared.global [%0], [%1], 16;" :: "r"(dst_u32), "l"(src_ptr))
#define CP_COMMIT() asm volatile("cp.async.commit_group;")

// 4-stage pipelines, dynamic shared memory
#define NN_AS 5120   // 128*40 elems per stage
#define NN_BS 4352   // 32*136
#define NT_AS 5120
#define NT_BS 5120
#define NN_SMEM (4 * (NN_AS + NN_BS) * 2)   // 75776 B
#define NT_SMEM (4 * (NT_AS + NT_BS) * 2)   // 81920 B

// acc: 0 = store, 1 = +=, 2 = atomicAdd (C pre-zeroed; split-K)
// ---------------- NN GEMM: C(MxN) = A(MxK) @ B(KxN), bf16->fp32 ----------------
__global__ void __launch_bounds__(256) hgemm_nn(int M, int N, int K,
        const __nv_bfloat16* __restrict__ A, int lda,
        const __nv_bfloat16* __restrict__ B, int ldb,
        float* __restrict__ C, int ldc, int acc) {
    extern __shared__ __nv_bfloat16 dsm[];
    __nv_bfloat16* Asm = dsm;             // 4*NN_AS
    __nv_bfloat16* Bsm = dsm + 4 * NN_AS; // 4*NN_BS
    const int tid  = threadIdx.x;
    const int lane = tid & 31;
    const int warp = tid >> 5;
    const int wm = (warp >> 2) * 64;
    const int wn = (warp & 3) * 32;
    const int m0 = blockIdx.y * 128;
    const int n0 = blockIdx.x * 128;
    const int Kc = K / gridDim.z;
    const int k0 = blockIdx.z * Kc;

    const int ar = tid >> 1, ac = (tid & 1) * 16;
    const int br = tid >> 3, bc = (tid & 7) * 16;

    float c[4][4][4];
#pragma unroll
    for (int mt = 0; mt < 4; mt++)
#pragma unroll
        for (int nt = 0; nt < 4; nt++)
#pragma unroll
            for (int r = 0; r < 4; r++) c[mt][nt][r] = 0.f;

    const int ntile = Kc >> 5;

#define NN_LOAD(s, kk) { \
    unsigned da = (unsigned)__cvta_generic_to_shared(Asm + (s) * NN_AS + ar * 40 + ac); \
    const __nv_bfloat16* pa = A + (size_t)(m0 + ar) * lda + (kk) + ac; \
    CPASYNC16(da, pa); CPASYNC16(da + 16, pa + 8); \
    unsigned db = (unsigned)__cvta_generic_to_shared(Bsm + (s) * NN_BS + br * 136 + bc); \
    const __nv_bfloat16* pb = B + (size_t)((kk) + br) * ldb + n0 + bc; \
    CPASYNC16(db, pb); CPASYNC16(db + 16, pb + 8); }

    for (int p = 0; p < 3; ++p) {
        if (p < ntile) NN_LOAD(p, k0 + p * 32);
        CP_COMMIT();
    }

    for (int it = 0; it < ntile; ++it) {
        asm volatile("cp.async.wait_group 2;");
        __syncthreads();
        int pf = it + 3;
        if (pf < ntile) NN_LOAD(pf & 3, k0 + pf * 32);
        CP_COMMIT();

        const int s = it & 3;
        const __nv_bfloat16* As_s = Asm + s * NN_AS;
        const __nv_bfloat16* Bs_s = Bsm + s * NN_BS;
#pragma unroll
        for (int ks = 0; ks < 32; ks += 16) {
            uint32_t af[4][4];
#pragma unroll
            for (int mt = 0; mt < 4; mt++) {
                unsigned addr = (unsigned)__cvta_generic_to_shared(
                    As_s + (wm + mt * 16 + (lane & 15)) * 40 + ks + (lane >> 4) * 8);
                asm volatile("ldmatrix.sync.aligned.m8n8.x4.shared.b16 {%0,%1,%2,%3}, [%4];"
                    : "=r"(af[mt][0]), "=r"(af[mt][1]), "=r"(af[mt][2]), "=r"(af[mt][3])
                    : "r"(addr));
            }
            uint32_t bfr[4][2];
#pragma unroll
            for (int nt = 0; nt < 4; nt++) {
                unsigned addr = (unsigned)__cvta_generic_to_shared(
                    Bs_s + (ks + (lane & 15)) * 136 + wn + nt * 8);
                asm volatile("ldmatrix.sync.aligned.m8n8.x2.trans.shared.b16 {%0,%1}, [%2];"
                    : "=r"(bfr[nt][0]), "=r"(bfr[nt][1]) : "r"(addr));
            }
#pragma unroll
            for (int mt = 0; mt < 4; mt++)
#pragma unroll
                for (int nt = 0; nt < 4; nt++)
                    asm volatile(
                        "mma.sync.aligned.m16n8k16.row.col.f32.bf16.bf16.f32 "
                        "{%0,%1,%2,%3}, {%4,%5,%6,%7}, {%8,%9}, {%0,%1,%2,%3};"
                        : "+f"(c[mt][nt][0]), "+f"(c[mt][nt][1]),
                          "+f"(c[mt][nt][2]), "+f"(c[mt][nt][3])
                        : "r"(af[mt][0]), "r"(af[mt][1]), "r"(af[mt][2]), "r"(af[mt][3]),
                          "r"(bfr[nt][0]), "r"(bfr[nt][1]));
        }
        __syncthreads();
    }

    const int r0 = lane >> 2, c0 = (lane & 3) * 2;
#pragma unroll
    for (int mt = 0; mt < 4; mt++)
#pragma unroll
        for (int nt = 0; nt < 4; nt++) {
            int row = m0 + wm + mt * 16 + r0;
            int col = n0 + wn + nt * 8 + c0;
            float* p0 = C + (size_t)row * ldc + col;
            float* p1 = C + (size_t)(row + 8) * ldc + col;
            if (acc == 2) {
                atomicAdd(p0,     c[mt][nt][0]); atomicAdd(p0 + 1, c[mt][nt][1]);
                atomicAdd(p1,     c[mt][nt][2]); atomicAdd(p1 + 1, c[mt][nt][3]);
            } else if (acc == 1) {
                p0[0] += c[mt][nt][0]; p0[1] += c[mt][nt][1];
                p1[0] += c[mt][nt][2]; p1[1] += c[mt][nt][3];
            } else {
                p0[0] = c[mt][nt][0]; p0[1] = c[mt][nt][1];
                p1[0] = c[mt][nt][2]; p1[1] = c[mt][nt][3];
            }
        }
}

// ---------------- NT GEMM: C(MxN) = A(MxK) @ B(NxK)^T, bf16->fp32 ----------------
__global__ void __launch_bounds__(256) hgemm_nt(int M, int N, int K,
        const __nv_bfloat16* __restrict__ A, int lda,
        const __nv_bfloat16* __restrict__ B, int ldb,
        float* __restrict__ C, int ldc, int acc) {
    extern __shared__ __nv_bfloat16 dsm[];
    __nv_bfloat16* Asm = dsm;
    __nv_bfloat16* Bsm = dsm + 4 * NT_AS;
    const int tid  = threadIdx.x;
    const int lane = tid & 31;
    const int warp = tid >> 5;
    const int wm = (warp >> 2) * 64;
    const int wn = (warp & 3) * 32;
    const int m0 = blockIdx.y * 128;
    const int n0 = blockIdx.x * 128;
    const int Kc = K / gridDim.z;
    const int k0 = blockIdx.z * Kc;

    const int ar = tid >> 1, ac = (tid & 1) * 16;

    float c[4][4][4];
#pragma unroll
    for (int mt = 0; mt < 4; mt++)
#pragma unroll
        for (int nt = 0; nt < 4; nt++)
#pragma unroll
            for (int r = 0; r < 4; r++) c[mt][nt][r] = 0.f;

    const int ntile = Kc >> 5;

#define NT_LOAD(s, kk) { \
    unsigned da = (unsigned)__cvta_generic_to_shared(Asm + (s) * NT_AS + ar * 40 + ac); \
    const __nv_bfloat16* pa = A + (size_t)(m0 + ar) * lda + (kk) + ac; \
    CPASYNC16(da, pa); CPASYNC16(da + 16, pa + 8); \
    unsigned db = (unsigned)__cvta_generic_to_shared(Bsm + (s) * NT_BS + ar * 40 + ac); \
    const __nv_bfloat16* pb = B + (size_t)(n0 + ar) * ldb + (kk) + ac; \
    CPASYNC16(db, pb); CPASYNC16(db + 16, pb + 8); }

    for (int p = 0; p < 3; ++p) {
        if (p < ntile) NT_LOAD(p, k0 + p * 32);
        CP_COMMIT();
    }

    for (int it = 0; it < ntile; ++it) {
        asm volatile("cp.async.wait_group 2;");
        __syncthreads();
        int pf = it + 3;
        if (pf < ntile) NT_LOAD(pf & 3, k0 + pf * 32);
        CP_COMMIT();

        const int s = it & 3;
        const __nv_bfloat16* As_s = Asm + s * NT_AS;
        const __nv_bfloat16* Bs_s = Bsm + s * NT_BS;
#pragma unroll
        for (int ks = 0; ks < 32; ks += 16) {
            uint32_t af[4][4];
#pragma unroll
            for (int mt = 0; mt < 4; mt++) {
                unsigned addr = (unsigned)__cvta_generic_to_shared(
                    As_s + (wm + mt * 16 + (lane & 15)) * 40 + ks + (lane >> 4) * 8);
                asm volatile("ldmatrix.sync.aligned.m8n8.x4.shared.b16 {%0,%1,%2,%3}, [%4];"
                    : "=r"(af[mt][0]), "=r"(af[mt][1]), "=r"(af[mt][2]), "=r"(af[mt][3])
                    : "r"(addr));
            }
            uint32_t bfr[4][2];
#pragma unroll
            for (int nt = 0; nt < 4; nt++) {
                unsigned addr = (unsigned)__cvta_generic_to_shared(
                    Bs_s + (wn + nt * 8 + (lane & 7)) * 40 + ks + ((lane >> 3) & 1) * 8);
                asm volatile("ldmatrix.sync.aligned.m8n8.x2.shared.b16 {%0,%1}, [%2];"
                    : "=r"(bfr[nt][0]), "=r"(bfr[nt][1]) : "r"(addr));
            }
#pragma unroll
            for (int mt = 0; mt < 4; mt++)
#pragma unroll
                for (int nt = 0; nt < 4; nt++)
                    asm volatile(
                        "mma.sync.aligned.m16n8k16.row.col.f32.bf16.bf16.f32 "
                        "{%0,%1,%2,%3}, {%4,%5,%6,%7}, {%8,%9}, {%0,%1,%2,%3};"
                        : "+f"(c[mt][nt][0]), "+f"(c[mt][nt][1]),
                          "+f"(c[mt][nt][2]), "+f"(c[mt][nt][3])
                        : "r"(af[mt][0]), "r"(af[mt][1]), "r"(af[mt][2]), "r"(af[mt][3]),
                          "r"(bfr[nt][0]), "r"(bfr[nt][1]));
        }
        __syncthreads();
    }

    const int r0 = lane >> 2, c0 = (lane & 3) * 2;
#pragma unroll
    for (int mt = 0; mt < 4; mt++)
#pragma unroll
        for (int nt = 0; nt < 4; nt++) {
            int row = m0 + wm + mt * 16 + r0;
            int col = n0 + wn + nt * 8 + c0;
            float* p0 = C + (size_t)row * ldc + col;
            float* p1 = C + (size_t)(row + 8) * ldc + col;
            if (acc == 2) {
                atomicAdd(p0,     c[mt][nt][0]); atomicAdd(p0 + 1, c[mt][nt][1]);
                atomicAdd(p1,     c[mt][nt][2]); atomicAdd(p1 + 1, c[mt][nt][3]);
            } else if (acc == 1) {
                p0[0] += c[mt][nt][0]; p0[1] += c[mt][nt][1];
                p1[0] += c[mt][nt][2]; p1[1] += c[mt][nt][3];
            } else {
                p0[0] = c[mt][nt][0]; p0[1] = c[mt][nt][1];
                p1[0] = c[mt][nt][2]; p1[1] = c[mt][nt][3];
            }
        }
}

// ---------------- SGEMM (fp32 SIMT) with optional fused bias+act ----------------
__global__ void __launch_bounds__(256) sgemm(int M, int N, int K,
                                             const float* __restrict__ A,
                                             const float* __restrict__ B,
                                             const float* __restrict__ bias,
                                             float* __restrict__ C, int act) {
    __shared__ float As[8][128];
    __shared__ float Bs[8][128];
    const int tid  = threadIdx.x;
    const int tx   = tid & 15;
    const int ty   = tid >> 4;
    const int row0 = blockIdx.y * 128;
    const int col0 = blockIdx.x * 128;
    const int a_row = tid >> 1, a_col = (tid & 1) << 2;
    const int b_row = tid >> 5, b_col = (tid & 31) << 2;

    float acc[8][8];
#pragma unroll
    for (int i = 0; i < 8; i++)
#pragma unroll
        for (int j = 0; j < 8; j++) acc[i][j] = 0.f;

    for (int kk = 0; kk < K; kk += 8) {
        float4 av = make_float4(0.f, 0.f, 0.f, 0.f);
        {
            int gm = row0 + a_row, gk = kk + a_col;
            if (gm < M && gk < K)
                av = *reinterpret_cast<const float4*>(A + (size_t)gm * K + gk);
        }
        As[a_col + 0][a_row] = av.x;
        As[a_col + 1][a_row] = av.y;
        As[a_col + 2][a_row] = av.z;
        As[a_col + 3][a_row] = av.w;

        float4 bv = make_float4(0.f, 0.f, 0.f, 0.f);
        {
            int gk = kk + b_row, gn = col0 + b_col;
            if (gk < K && gn < N)
                bv = *reinterpret_cast<const float4*>(B + (size_t)gk * N + gn);
        }
        *reinterpret_cast<float4*>(&Bs[b_row][b_col]) = bv;
        __syncthreads();

#pragma unroll
        for (int k = 0; k < 8; k++) {
            float4 a0 = *reinterpret_cast<const float4*>(&As[k][ty * 8]);
            float4 a1 = *reinterpret_cast<const float4*>(&As[k][ty * 8 + 4]);
            float4 b0 = *reinterpret_cast<const float4*>(&Bs[k][tx * 8]);
            float4 b1 = *reinterpret_cast<const float4*>(&Bs[k][tx * 8 + 4]);
            float a[8] = {a0.x, a0.y, a0.z, a0.w, a1.x, a1.y, a1.z, a1.w};
            float b[8] = {b0.x, b0.y, b0.z, b0.w, b1.x, b1.y, b1.z, b1.w};
#pragma unroll
            for (int i = 0; i < 8; i++)
#pragma unroll
                for (int j = 0; j < 8; j++) acc[i][j] += a[i] * b[j];
        }
        __syncthreads();
    }

#pragma unroll
    for (int i = 0; i < 8; i++) {
        int gm = row0 + ty * 8 + i;
        if (gm >= M) continue;
        float* Cr = C + (size_t)gm * N;
#pragma unroll
        for (int j = 0; j < 8; j++) {
            int gn = col0 + tx * 8 + j;
            if (gn >= N) continue;
            float v = acc[i][j];
            if (bias) v += bias[gn];
            if (act == ACT_RELU) v = fmaxf(v, 0.f);
            else if (act == ACT_SIGM) v = 1.f / (1.f + expf(-v));
            Cr[gn] = v;
        }
    }
}

// ---------------- elementwise / graph kernels ----------------
__global__ void k_edges_b(const int* __restrict__ ei, int E, __nv_bfloat16* __restrict__ A) {
    int e = blockIdx.x * blockDim.x + threadIdx.x;
    if (e >= E) return;
    int s = ei[e], d = ei[E + e];
    __nv_bfloat16 one = __float2bfloat16(1.f);
    A[(size_t)s * N0 + d] = one;
    A[(size_t)d * N0 + s] = one;
}

__global__ void k_diag1_b(__nv_bfloat16* __restrict__ A, int n, int ld) {
    int i = blockIdx.x * blockDim.x + threadIdx.x;
    if (i < n) {
        size_t p = (size_t)i * ld + i;
        A[p] = __float2bfloat16(__bfloat162float(A[p]) + 1.f);
    }
}

// dis[row] = rsqrt(rowsum of bf16 matrix row, width w) — matrix already contains +I
__global__ void k_dis_b(const __nv_bfloat16* __restrict__ M, int ld, int w,
                        float* __restrict__ dis) {
    __shared__ float red[256];
    int row = blockIdx.x;
    const __nv_bfloat16* Mr = M + (size_t)row * ld;
    float s = 0.f;
    for (int j = threadIdx.x; j < w; j += 256) s += __bfloat162float(Mr[j]);
    red[threadIdx.x] = s;
    __syncthreads();
    for (int o = 128; o > 0; o >>= 1) {
        if (threadIdx.x < o) red[threadIdx.x] += red[threadIdx.x + o];
        __syncthreads();
    }
    if (threadIdx.x == 0) dis[row] = rsqrtf(red[0]);
}

// packed z: zpk (np x 2Cpad) = [hi(dis*xw) | lo(dis*xw)]
__global__ void k_scale_pack(const float* __restrict__ xw, const float* __restrict__ dis,
                             int n, int np, int C, int Cpad,
                             __nv_bfloat16* __restrict__ zpk) {
    int i = blockIdx.x * blockDim.x + threadIdx.x;
    int W = 2 * Cpad;
    if (i >= np * W) return;
    int r = i / W, cc = i - r * W;
    int col = (cc < Cpad) ? cc : cc - Cpad;
    float v = (r < n && col < C) ? dis[r] * xw[(size_t)r * C + col] : 0.f;
    __nv_bfloat16 hi = __float2bfloat16(v);
    if (cc < Cpad) zpk[i] = hi;
    else           zpk[i] = __float2bfloat16(v - __bfloat162float(hi));
}

// packed stacked z: Bp (2np x 2C); rows<np: [hi|lo], rows>=np: [lo|hi]
__global__ void k_scale_pack_stk(const float* __restrict__ xw, const float* __restrict__ dis,
                                 int n, int np, int C,
                                 __nv_bfloat16* __restrict__ Bp) {
    int i = blockIdx.x * blockDim.x + threadIdx.x;
    int W = 2 * C;
    if (i >= 2 * np * W) return;
    int r = i / W, cc = i - r * W;
    int rr = (r < np) ? r : r - np;
    int col = (cc < C) ? cc : cc - C;
    float v = (rr < n) ? dis[rr] * xw[(size_t)rr * C + col] : 0.f;
    __nv_bfloat16 hi = __float2bfloat16(v);
    __nv_bfloat16 lo = __float2bfloat16(v - __bfloat162float(hi));
    bool wantHi = ((r < np) == (cc < C));
    Bp[i] = wantHi ? hi : lo;
}

// out = act(dis*(t[cc] + t[cc+half]) + b)
__global__ void k_epilogue_sum2(const float* __restrict__ t, int ldt, int half,
                                const float* __restrict__ dis, const float* __restrict__ b,
                                int n, int C, float* __restrict__ out, int act) {
    int i = blockIdx.x * blockDim.x + threadIdx.x;
    if (i >= n * C) return;
    int r = i / C, cc = i - r * C;
    float v = dis[r] * (t[(size_t)r * ldt + cc] + t[(size_t)r * ldt + cc + half]) + b[cc];
    if (act == ACT_RELU) v = fmaxf(v, 0.f);
    else if (act == ACT_SIGM) v = 1.f / (1.f + expf(-v));
    out[i] = v;
}

// S[r][c] = dis[r]*(t[r*ldt+c] + t[r*ldt+c+half])  (level-0 reorder intermediate)
__global__ void k_sum2_scale(const float* __restrict__ t, int ldt, int half,
                             const float* __restrict__ dis, int n, int C,
                             float* __restrict__ S) {
    int i = blockIdx.x * blockDim.x + threadIdx.x;
    if (i >= n * C) return;
    int r = i / C, cc = i - r * C;
    S[i] = dis[r] * (t[(size_t)r * ldt + cc] + t[(size_t)r * ldt + cc + half]);
}

// bA (np x np) = bf16 of cropped Augp + I  (small-int entries, exact)
__global__ void k_crop_tobf16(const float* __restrict__ Augp, int kpad, int k, int np,
                              __nv_bfloat16* __restrict__ bA) {
    int i = blockIdx.x * blockDim.x + threadIdx.x;
    if (i >= np * np) return;
    int r = i / np, cc = i - r * np;
    float v = 0.f;
    if (r < k && cc < k) v = (r == cc) ? 1.f : Augp[(size_t)r * kpad + cc];
    bA[i] = __float2bfloat16(v);
}

// X (np x 2np) = [hi | lo] of cropped Augp + I (exact hi/lo split)
__global__ void k_crop_pack_X(const float* __restrict__ Augp, int kpad, int k, int np,
                              __nv_bfloat16* __restrict__ X) {
    int i = blockIdx.x * blockDim.x + threadIdx.x;
    if (i >= np * np) return;
    int r = i / np, cc = i - r * np;
    float v = 0.f;
    if (r < k && cc < k) v = (r == cc) ? 1.f : Augp[(size_t)r * kpad + cc];
    __nv_bfloat16 hi = __float2bfloat16(v);
    __nv_bfloat16 lo = __float2bfloat16(v - __bfloat162float(hi));
    X[(size_t)r * (2 * np) + cc]      = hi;
    X[(size_t)r * (2 * np) + np + cc] = lo;
}

// G[r][:] = bApI[perm[r]][:]  (kpad x np)
__global__ void k_gather_rows(const __nv_bfloat16* __restrict__ bApI, int np,
                              const int* __restrict__ perm, int k, int kpad,
                              __nv_bfloat16* __restrict__ G) {
    int i = blockIdx.x * blockDim.x + threadIdx.x;
    if (i >= kpad * np) return;
    int r = i / np, j = i - r * np;
    G[i] = (r < k) ? bApI[(size_t)perm[r] * np + j] : __float2bfloat16(0.f);
}

// P = gather rows of X2 ([hi|lo]); Q = same with halves swapped ([lo|hi])
__global__ void k_gather_PQ_b(const __nv_bfloat16* __restrict__ X2, int np,
                              const int* __restrict__ perm, int k, int kpad,
                              __nv_bfloat16* __restrict__ P,
                              __nv_bfloat16* __restrict__ Q) {
    int i = blockIdx.x * blockDim.x + threadIdx.x;
    int W = 2 * np;
    if (i >= kpad * W) return;
    int r = i / W, j = i - r * W;
    __nv_bfloat16 v = (r < k) ? X2[(size_t)perm[r] * W + j] : __float2bfloat16(0.f);
    P[i] = v;
    int js = (j < np) ? j + np : j - np;
    Q[(size_t)r * W + js] = v;
}

__global__ void k_pnorm(const float* __restrict__ p, int n, float* __restrict__ out) {
    __shared__ float red[256];
    float s = 0.f;
    for (int i = threadIdx.x; i < n; i += 256) s += p[i] * p[i];
    red[threadIdx.x] = s;
    __syncthreads();
    for (int o = 128; o > 0; o >>= 1) {
        if (threadIdx.x < o) red[threadIdx.x] += red[threadIdx.x + o];
        __syncthreads();
    }
    if (threadIdx.x == 0) out[0] = sqrtf(red[0]);
}

__global__ void k_scores(const float* __restrict__ h, int n, int C,
                         const float* __restrict__ p, const float* __restrict__ pn,
                         float* __restrict__ score) {
    int row = blockIdx.x * 8 + (threadIdx.x >> 5);
    int lane = threadIdx.x & 31;
    if (row >= n) return;
    const float* hr = h + (size_t)row * C;
    float s = 0.f;
    for (int cc = lane; cc < C; cc += 32) s += hr[cc] * p[cc];
    for (int o = 16; o > 0; o >>= 1) s += __shfl_xor_sync(0xffffffffu, s, o);
    if (lane == 0) score[row] = tanhf(s / pn[0]);
}

__global__ void __launch_bounds__(1024) k_sort_topk(const float* __restrict__ score,
                                                    int n, int npad, int k,
                                                    int* __restrict__ perm) {
    __shared__ float skey[4096];
    __shared__ int   sidx[4096];
    for (int i = threadIdx.x; i < npad; i += blockDim.x) {
        skey[i] = (i < n) ? score[i] : -INFINITY;
        sidx[i] = i;
    }
    __syncthreads();
    for (int kk = 2; kk <= npad; kk <<= 1) {
        for (int j = kk >> 1; j > 0; j >>= 1) {
            for (int i = threadIdx.x; i < npad; i += blockDim.x) {
                int ixj = i ^ j;
                if (ixj > i) {
                    float a = skey[i], b = skey[ixj];
                    bool sw = ((i & kk) == 0) ? (a < b) : (a > b);
                    if (sw) {
                        skey[i] = b; skey[ixj] = a;
                        int t = sidx[i]; sidx[i] = sidx[ixj]; sidx[ixj] = t;
                    }
                }
            }
            __syncthreads();
        }
    }
    for (int i = threadIdx.x; i < k; i += blockDim.x) perm[i] = sidx[i];
}

__global__ void k_gatherX(const float* __restrict__ h, int C,
                          const int* __restrict__ perm, const float* __restrict__ score,
                          int k, float* __restrict__ out) {
    int i = blockIdx.x * blockDim.x + threadIdx.x;
    if (i >= k * C) return;
    int r = i / C, cc = i - r * C;
    int pr = perm[r];
    out[i] = h[(size_t)pr * C + cc] * score[pr];
}

__global__ void k_scatter_add(float* __restrict__ u, const float* __restrict__ h,
                              const int* __restrict__ perm, int k, int C) {
    int i = blockIdx.x * blockDim.x + threadIdx.x;
    if (i >= k * C) return;
    int r = i / C, cc = i - r * C;
    u[(size_t)perm[r] * C + cc] += h[i];
}

// ---------------- host orchestration ----------------
static void run_sgemm(int M, int N, int K, const float* A, const float* B,
                      const float* bias, float* C, int act) {
    dim3 g((N + 127) / 128, (M + 127) / 128);
    sgemm<<<g, 256>>>(M, N, K, A, B, bias, C, act);
}
static void run_nn(int M, int N, int K, const __nv_bfloat16* A, int lda,
                   const __nv_bfloat16* B, int ldb, float* C, int ldc, int acc, int splitk) {
    cudaFuncSetAttribute(hgemm_nn, cudaFuncAttributeMaxDynamicSharedMemorySize, NN_SMEM);
    dim3 g(N / 128, M / 128, splitk);
    hgemm_nn<<<g, 256, NN_SMEM>>>(M, N, K, A, lda, B, ldb, C, ldc, acc);
}
static void run_nt(int M, int N, int K, const __nv_bfloat16* A, int lda,
                   const __nv_bfloat16* B, int ldb, float* C, int ldc, int acc, int splitk) {
    cudaFuncSetAttribute(hgemm_nt, cudaFuncAttributeMaxDynamicSharedMemorySize, NT_SMEM);
    dim3 g(N / 128, M / 128, splitk);
    hgemm_nt<<<g, 256, NT_SMEM>>>(M, N, K, A, lda, B, ldb, C, ldc, acc);
}

// exact-bf16 adjacency GCN (XW-first order)
static void run_gcn_exact(const __nv_bfloat16* bApI, int n, int np,
                          const float* X, int inC, const float* W, int outC, const float* b,
                          float* out, int act, int splitk,
                          float* xw, float* t, float* dis, __nv_bfloat16* zpk) {
    run_sgemm(n, outC, inC, X, W, nullptr, xw, ACT_NONE);
    k_dis_b<<<n, 256>>>(bApI, np, np, dis);
    int Cpad = (outC % 128 == 0) ? outC : 128;
    int W2 = 2 * Cpad;
    int tot = np * W2;
    k_scale_pack<<<(tot + 255) / 256, 256>>>(xw, dis, n, np, outC, Cpad, zpk);
    cudaMemsetAsync(t, 0, (size_t)np * W2 * sizeof(float), 0);
    run_nn(np, W2, np, bApI, np, zpk, W2, t, W2, 2, splitk);
    int nc = n * outC;
    k_epilogue_sum2<<<(nc + 255) / 256, 256>>>(t, W2, Cpad, dis, b, n, outC, out, act);
}

// split-adjacency GCN
static void run_gcn_split(const __nv_bfloat16* X2, int n, int np,
                          const float* X, int inC, const float* W, int outC, const float* b,
                          float* out, int act, int splitk,
                          float* xw, float* t, float* dis, __nv_bfloat16* Bp) {
    run_sgemm(n, outC, inC, X, W, nullptr, xw, ACT_NONE);
    k_dis_b<<<n, 256>>>(X2, 2 * np, 2 * np, dis);
    int W2 = 2 * outC;
    int tot = 2 * np * W2;
    k_scale_pack_stk<<<(tot + 255) / 256, 256>>>(xw, dis, n, np, outC, Bp);
    cudaMemsetAsync(t, 0, (size_t)np * W2 * sizeof(float), 0);
    run_nn(np, W2, 2 * np, X2, 2 * np, Bp, W2, t, W2, 2, splitk);
    int nc = n * outC;
    k_epilogue_sum2<<<(nc + 255) / 256, 256>>>(t, W2, outC, dis, b, n, outC, out, act);
}

static void run_scores_sort(const float* h, int n, int npad, const float* p, int k,
                            int* perm, float* score, float* pn) {
    k_pnorm<<<1, 256>>>(p, HC, pn);
    k_scores<<<(n + 7) / 8, 256>>>(h, n, HC, p, pn, score);
    k_sort_topk<<<1, 1024>>>(score, n, npad, k, perm);
}

extern "C" void kernel_launch(void* const* d_in, const int* in_sizes, int n_in,
                              void* d_out, int out_size) {
    const float* x   = (const float*)d_in[0];
    const int*   ei  = (const int*)  d_in[1];
    const float* Wd0 = (const float*)d_in[2];  const float* bd0 = (const float*)d_in[3];
    const float* Wd1 = (const float*)d_in[4];  const float* bd1 = (const float*)d_in[5];
    const float* Wd2 = (const float*)d_in[6];  const float* bd2 = (const float*)d_in[7];
    const float* Wd3 = (const float*)d_in[8];  const float* bd3 = (const float*)d_in[9];
    const float* p1  = (const float*)d_in[10];
    const float* p2  = (const float*)d_in[11];
    const float* p3  = (const float*)d_in[12];
    const float* Wu0 = (const float*)d_in[13]; const float* bu0 = (const float*)d_in[14];
    const float* Wu1 = (const float*)d_in[15]; const float* bu1 = (const float*)d_in[16];
    const float* Wu2 = (const float*)d_in[17]; const float* bu2 = (const float*)d_in[18];
    const int E = in_sizes[1] / 2;

    float *Augp, *h0, *h1, *h2, *h3, *hb, *xw, *t, *u, *dis, *sc, *pn;
    int *pm0, *pm1, *pm2;
    __nv_bfloat16 *bA0, *bA1, *bX2, *bX3, *G, *Q, *zpk;
    cudaGetSymbolAddress((void**)&Augp, g_Augp);
    cudaGetSymbolAddress((void**)&h0,  g_h0);
    cudaGetSymbolAddress((void**)&h1,  g_h1);
    cudaGetSymbolAddress((void**)&h2,  g_h2);
    cudaGetSymbolAddress((void**)&h3,  g_h3);
    cudaGetSymbolAddress((void**)&hb,  g_hb);
    cudaGetSymbolAddress((void**)&xw,  g_xw);
    cudaGetSymbolAddress((void**)&t,   g_t);
    cudaGetSymbolAddress((void**)&u,   g_u);
    cudaGetSymbolAddress((void**)&dis, g_dis);
    cudaGetSymbolAddress((void**)&sc,  g_sc);
    cudaGetSymbolAddress((void**)&pn,  g_pn);
    cudaGetSymbolAddress((void**)&pm0, g_perm0);
    cudaGetSymbolAddress((void**)&pm1, g_perm1);
    cudaGetSymbolAddress((void**)&pm2, g_perm2);
    cudaGetSymbolAddress((void**)&bA0, g_bA0);
    cudaGetSymbolAddress((void**)&bA1, g_bA1);
    cudaGetSymbolAddress((void**)&bX2, g_bX2);
    cudaGetSymbolAddress((void**)&bX3, g_bX3);
    cudaGetSymbolAddress((void**)&G,   g_G);
    cudaGetSymbolAddress((void**)&Q,   g_Q);
    cudaGetSymbolAddress((void**)&zpk, g_zpk);

    // ---- build bf16(A0+I) directly ----
    cudaMemsetAsync(bA0, 0, (size_t)N0 * N0 * sizeof(__nv_bfloat16), 0);
    k_edges_b<<<(E + 255) / 256, 256>>>(ei, E, bA0);
    k_diag1_b<<<(N0 + 255) / 256, 256>>>(bA0, N0, N0);

    // ---- down path: level 0, adjacency-first order (inC=128 << 512) ----
    // S = D(A+I)D x  (via hi/lo split), then h0 = relu(S @ Wd0 + bd0)
    k_dis_b<<<N0, 256>>>(bA0, N0, N0, dis);
    k_scale_pack<<<(N0 * 256 + 255) / 256, 256>>>(x, dis, N0, N0, INC, INC, zpk);
    cudaMemsetAsync(t, 0, (size_t)N0 * 256 * sizeof(float), 0);
    run_nn(N0, 256, N0, bA0, N0, zpk, 256, t, 256, 2, 4);
    k_sum2_scale<<<(N0 * INC + 255) / 256, 256>>>(t, 256, INC, dis, N0, INC, xw);
    run_sgemm(N0, HC, INC, xw, Wd0, bd0, h0, ACT_RELU);

    // pool0: A1 = [(A0+I)^2]_{perm0,perm0} = G@G^T, diag->0, +I -> bA1
    run_scores_sort(h0, N0, 4096, p1, KP1, pm0, sc, pn);
    k_gather_rows<<<(2048 * 4096 + 255) / 256, 256>>>(bA0, 4096, pm0, KP1, 2048, G);
    run_nt(2048, 2048, 4096, G, 4096, G, 4096, Augp, 2048, 0, 1);
    k_gatherX<<<(KP1 * HC + 255) / 256, 256>>>(h0, HC, pm0, sc, KP1, u);
    k_crop_tobf16<<<(2048 * 2048 + 255) / 256, 256>>>(Augp, 2048, KP1, 2048, bA1);
    run_gcn_exact(bA1, KP1, 2048, u, HC, Wd1, HC, bd1, h1, ACT_RELU, 4,
                  xw, t, dis, zpk);

    // pool1: A2 submatrix via G@G^T (split-K), -> bX2 split
    run_scores_sort(h1, KP1, 2048, p2, KP2, pm1, sc, pn);
    k_gather_rows<<<(1024 * 2048 + 255) / 256, 256>>>(bA1, 2048, pm1, KP2, 1024, G);
    cudaMemsetAsync(Augp, 0, (size_t)1024 * 1024 * sizeof(float), 0);
    run_nt(1024, 1024, 2048, G, 2048, G, 2048, Augp, 1024, 2, 2);
    k_gatherX<<<(KP2 * HC + 255) / 256, 256>>>(h1, HC, pm1, sc, KP2, u);
    k_crop_pack_X<<<(1024 * 1024 + 255) / 256, 256>>>(Augp, 1024, KP2, 1024, bX2);
    run_gcn_split(bX2, KP2, 1024, u, HC, Wd2, HC, bd2, h2, ACT_RELU, 4,
                  xw, t, dis, zpk);

    // pool2: A3 = P@P^T + P@Q^T (exact hi/lo split), -> bX3 split
    run_scores_sort(h2, KP2, 1024, p3, KP3, pm2, sc, pn);
    k_gather_PQ_b<<<(512 * 2048 + 255) / 256, 256>>>(bX2, 1024, pm2, KP3, 512, G, Q);
    cudaMemsetAsync(Augp, 0, (size_t)512 * 512 * sizeof(float), 0);
    run_nt(512, 512, 2048, G, 2048, G, 2048, Augp, 512, 2, 4);
    run_nt(512, 512, 2048, G, 2048, Q, 2048, Augp, 512, 2, 4);
    k_gatherX<<<(KP3 * HC + 255) / 256, 256>>>(h2, HC, pm2, sc, KP3, u);
    k_crop_pack_X<<<(512 * 512 + 255) / 256, 256>>>(Augp, 512, KP3, 512, bX3);
    run_gcn_split(bX3, KP3, 512, u, HC, Wd3, HC, bd3, h3, ACT_RELU, 4,
                  xw, t, dis, zpk);

    // ---- up path ----
    cudaMemcpyAsync(u, h2, (size_t)KP2 * HC * sizeof(float), cudaMemcpyDeviceToDevice, 0);
    k_scatter_add<<<(KP3 * HC + 255) / 256, 256>>>(u, h3, pm2, KP3, HC);
    run_gcn_split(bX2, KP2, 1024, u, HC, Wu0, HC, bu0, hb, ACT_RELU, 4,
                  xw, t, dis, zpk);

    cudaMemcpyAsync(u, h1, (size_t)KP1 * HC * sizeof(float), cudaMemcpyDeviceToDevice, 0);
    k_scatter_add<<<(KP2 * HC + 255) / 256, 256>>>(u, hb, pm1, KP2, HC);
    run_gcn_exact(bA1, KP1, 2048, u, HC, Wu1, HC, bu1, hb, ACT_RELU, 4,
                  xw, t, dis, zpk);

    cudaMemcpyAsync(u, h0, (size_t)N0 * HC * sizeof(float), cudaMemcpyDeviceToDevice, 0);
    k_scatter_add<<<(KP1 * HC + 255) / 256, 256>>>(u, hb, pm0, KP1, HC);
    run_gcn_exact(bA0, N0, 4096, u, HC, Wu2, OC, bu2, (float*)d_out, ACT_SIGM, 4,
                  xw, t, dis, zpk);
}